// round 1
// baseline (speedup 1.0000x reference)
#include <cuda_runtime.h>
#include <math.h>

#define NN 4096
#define DD 256

// ---------------- device scratch (no allocations allowed) ----------------
__device__ float d_key[NN];
__device__ float d_nrmR[NN];
__device__ float d_nrmM[NN];
__device__ int   d_rank[NN];   // rank[i] = position of row i in ascending key order
__device__ int   d_sidx[NN];   // sidx[a]  = original row index of a-th smallest
__device__ float d_Gs[(size_t)NN * NN];  // G in sorted coordinates (upper triangle valid)

// ---------------- math helpers (epilogue; smooth, not bit-critical) ------
__device__ __forceinline__ float logitexp_f(float logp) {
    const float L2 = 0.69314718056f;
    float pos = fmaxf(logp, -L2);
    float neg = fminf(logp, -L2);
    float neg_val = neg - log1pf(-expf(neg));
    float pos_val = -logf(fmaxf(expm1f(-pos), 1e-20f));
    return pos_val + neg_val;
}

__device__ __forceinline__ float rbern(float logits, float u) {
    const float lo = 1e-6f;
    const float hi = (float)(1.0 - 1e-6);
    u = fminf(fmaxf(u, lo), hi);
    float logistic = logf(u) - log1pf(-u);
    float z = (logits + logistic) * (1.0f / 0.3f);
    return 1.0f / (1.0f + expf(-z));
}

// ---------------- K1: sort key (bit-exactness critical) + uR norms -------
// One block of 256 threads per row. Per-element ops mirror eager-JAX/XLA-GPU:
// div (RN), __nv_erff, mul (RN), add (RN), __nv_logf; reduction = intra-warp
// shfl_down tree (16..1) then inter-warp tree over 8 partials padded with 0.
__global__ void k_keyR(const float* __restrict__ uR) {
    int row = blockIdx.x;
    int t = threadIdx.x;
    float x = uR[row * DD + t];
    float q = __fdiv_rn(x, 1.41421356237309515f);
    float p = __fadd_rn(0.5f, __fmul_rn(0.5f, erff(q)));
    float v = logf(p);
    float n = x * x;
#pragma unroll
    for (int off = 16; off > 0; off >>= 1) {
        v = __fadd_rn(v, __shfl_down_sync(0xffffffffu, v, off));
        n += __shfl_down_sync(0xffffffffu, n, off);
    }
    __shared__ float wp[8], wn[8];
    int w = t >> 5, lane = t & 31;
    if (lane == 0) { wp[w] = v; wn[w] = n; }
    __syncthreads();
    if (w == 0) {
        float pv = (lane < 8) ? wp[lane] : 0.0f;
        float pn = (lane < 8) ? wn[lane] : 0.0f;
#pragma unroll
        for (int off = 16; off > 0; off >>= 1) {
            pv = __fadd_rn(pv, __shfl_down_sync(0xffffffffu, pv, off));
            pn += __shfl_down_sync(0xffffffffu, pn, off);
        }
        if (lane == 0) { d_key[row] = pv; d_nrmR[row] = pn; }
    }
}

// ---------------- K1b: uM row norms (order-insensitive) ------------------
__global__ void k_nrmM(const float* __restrict__ uM) {
    int w = (blockIdx.x * blockDim.x + threadIdx.x) >> 5;
    int lane = threadIdx.x & 31;
    if (w >= NN) return;
    const float* r = uM + w * DD;
    float n = 0.0f;
#pragma unroll
    for (int k = 0; k < DD / 32; k++) { float x = r[lane + 32 * k]; n = fmaf(x, x, n); }
#pragma unroll
    for (int off = 16; off > 0; off >>= 1) n += __shfl_down_sync(0xffffffffu, n, off);
    if (lane == 0) d_nrmM[w] = n;
}

// ---------------- K2: stable ranks via counting (O(N^2), trivial) --------
__global__ void k_rank() {
    __shared__ float keys[NN];
    int tid = threadIdx.x;
    for (int j = tid; j < NN; j += blockDim.x) keys[j] = d_key[j];
    __syncthreads();
    int i = blockIdx.x * blockDim.x + tid;
    float ki = keys[i];
    int r = 0;
    for (int j = 0; j < NN; j++) {
        float kj = keys[j];
        r += (kj < ki) || (kj == ki && j < i);
    }
    d_rank[i] = r;
    d_sidx[r] = i;
}

// ---------------- K3/K5: fused fp32 SGEMM + logitexp/bernoulli epilogue --
// 128x128 tile, BK=16, 256 threads, 8x8 per thread.
// TRI=true : G in sorted coords — rows/cols gathered via d_sidx, only tiles
//            with tb>=ta launched, only bJ>aI elements written to d_Gs.
// TRI=false: A = uM x uR^T, full grid, writes directly to out[1].
template<bool TRI>
__global__ void __launch_bounds__(256)
k_gemm_epi(const float* __restrict__ Am, const float* __restrict__ Bm,
           const float* __restrict__ U, const float* __restrict__ gls,
           float* __restrict__ OutA)
{
    __shared__ __align__(16) float As[16][132];
    __shared__ __align__(16) float Bs[16][132];
    __shared__ int   rA[128];
    __shared__ int   rB[128];
    __shared__ float snA[128];
    __shared__ float snB[128];

    int tid = threadIdx.x;
    int tx = tid & 15, ty = tid >> 4;

    int ta, tb;
    if (TRI) {
        int rem = blockIdx.x; ta = 0;
        while (rem >= (32 - ta)) { rem -= (32 - ta); ta++; }
        tb = ta + rem;
    } else { ta = blockIdx.y; tb = blockIdx.x; }
    int a0 = ta * 128, b0 = tb * 128;

    if (tid < 128) {
        int a = a0 + tid;
        int ra = TRI ? d_sidx[a] : a;
        rA[tid] = ra;
        snA[tid] = TRI ? d_nrmR[ra] : d_nrmM[ra];
    } else {
        int bi = tid - 128;
        int b = b0 + bi;
        int rb = TRI ? d_sidx[b] : b;
        rB[bi] = rb;
        snB[bi] = d_nrmR[rb];
    }
    __syncthreads();

    float acc[8][8];
#pragma unroll
    for (int i = 0; i < 8; i++)
#pragma unroll
        for (int j = 0; j < 8; j++) acc[i][j] = 0.0f;

    for (int k0 = 0; k0 < DD; k0 += 16) {
#pragma unroll
        for (int i = 0; i < 8; i++) {
            int idx = tid + i * 256;          // 0..2047
            int k = idx & 15, r = idx >> 4;
            As[k][r] = Am[rA[r] * DD + k0 + k];
            Bs[k][r] = Bm[rB[r] * DD + k0 + k];
        }
        __syncthreads();
#pragma unroll
        for (int kk = 0; kk < 16; kk++) {
            float av[8], bv[8];
            *(float4*)(av)     = *(const float4*)(&As[kk][ty * 8]);
            *(float4*)(av + 4) = *(const float4*)(&As[kk][ty * 8 + 4]);
            *(float4*)(bv)     = *(const float4*)(&Bs[kk][tx * 8]);
            *(float4*)(bv + 4) = *(const float4*)(&Bs[kk][tx * 8 + 4]);
#pragma unroll
            for (int i = 0; i < 8; i++)
#pragma unroll
                for (int j = 0; j < 8; j++)
                    acc[i][j] = fmaf(av[i], bv[j], acc[i][j]);
        }
        __syncthreads();
    }

    float scale = expf(gls[0]);
    float nhs = -0.5f / scale;
    float* outp = TRI ? d_Gs : OutA;

#pragma unroll
    for (int i = 0; i < 8; i++) {
        int aI = a0 + ty * 8 + i;
#pragma unroll
        for (int j = 0; j < 8; j++) {
            int bJ = b0 + tx * 8 + j;
            if (TRI && bJ <= aI) continue;
            float d2 = fmaxf((snA[ty * 8 + i] + snB[tx * 8 + j]) - 2.0f * acc[i][j], 0.0f);
            float logits = logitexp_f(d2 * nhs);
            float u = U[(size_t)aI * NN + bJ];
            outp[(size_t)aI * NN + bJ] = rbern(logits, u);
        }
    }
}

// ---------------- K4: permute G back to original row/col order -----------
// out0[i,j] = (rank_j > rank_i) ? Gs[rank_i, rank_j] : 0
__global__ void k_permG(float* __restrict__ out0) {
    __shared__ float rowbuf[NN];   // 16 KB: one sorted-coords row of Gs
    int i = blockIdx.x;
    int a = d_rank[i];
    const float* src = d_Gs + (size_t)a * NN;
    for (int j = threadIdx.x; j < NN; j += blockDim.x) rowbuf[j] = src[j];
    __syncthreads();
    float* dst = out0 + (size_t)i * NN;
    for (int j = threadIdx.x; j < NN; j += blockDim.x) {
        int rj = d_rank[j];
        dst[j] = (rj > a) ? rowbuf[rj] : 0.0f;
    }
}

// ---------------- launch ---------------------------------------------------
extern "C" void kernel_launch(void* const* d_in, const int* in_sizes, int n_in,
                              void* d_out, int out_size) {
    (void)in_sizes; (void)n_in; (void)out_size;
    const float* uR  = (const float*)d_in[0];
    const float* uM  = (const float*)d_in[1];
    const float* gls = (const float*)d_in[2];
    const float* uG  = (const float*)d_in[3];
    const float* uA  = (const float*)d_in[4];
    float* out = (float*)d_out;

    k_keyR<<<NN, 256>>>(uR);
    k_nrmM<<<NN / 8, 256>>>(uM);            // 512 blocks x 8 warps
    k_rank<<<NN / 256, 256>>>();

    // G (sorted coords, upper-triangle tiles only): 32*33/2 = 528 CTAs
    k_gemm_epi<true><<<528, 256>>>(uR, uR, uG, gls, nullptr);
    k_permG<<<NN, 256>>>(out);              // out[0] = G

    // A: full 32x32 grid of tiles
    dim3 gridA(32, 32);
    k_gemm_epi<false><<<gridA, 256>>>(uM, uR, uA, gls, out + (size_t)NN * NN);
}

// round 3
// speedup vs baseline: 2.4439x; 2.4439x over previous
#include <cuda_runtime.h>
#include <cuda_bf16.h>
#include <math.h>
#include <stdint.h>

#define NN 4096
#define DD 256

// ---------------- device scratch (no allocations allowed) ----------------
__device__ float d_key[NN];
__device__ float d_nrmR[NN];
__device__ float d_nrmM[NN];
__device__ int   d_rank[NN];
__device__ int   d_sidx[NN];
__device__ float d_Gs[(size_t)NN * NN];          // G in sorted coords
__device__ __nv_bfloat16 d_Rhi[(size_t)NN * DD];
__device__ __nv_bfloat16 d_Rlo[(size_t)NN * DD];
__device__ __nv_bfloat16 d_Mhi[(size_t)NN * DD];
__device__ __nv_bfloat16 d_Mlo[(size_t)NN * DD];

// ---------------- K1: sort key (BIT-EXACT — do not touch) + uR norms -----
__global__ void k_keyR(const float* __restrict__ uR) {
    int row = blockIdx.x;
    int t = threadIdx.x;
    float x = uR[row * DD + t];
    float q = __fdiv_rn(x, 1.41421356237309515f);
    float p = __fadd_rn(0.5f, __fmul_rn(0.5f, erff(q)));
    float v = logf(p);
    float n = x * x;
#pragma unroll
    for (int off = 16; off > 0; off >>= 1) {
        v = __fadd_rn(v, __shfl_down_sync(0xffffffffu, v, off));
        n += __shfl_down_sync(0xffffffffu, n, off);
    }
    __shared__ float wp[8], wn[8];
    int w = t >> 5, lane = t & 31;
    if (lane == 0) { wp[w] = v; wn[w] = n; }
    __syncthreads();
    if (w == 0) {
        float pv = (lane < 8) ? wp[lane] : 0.0f;
        float pn = (lane < 8) ? wn[lane] : 0.0f;
#pragma unroll
        for (int off = 16; off > 0; off >>= 1) {
            pv = __fadd_rn(pv, __shfl_down_sync(0xffffffffu, pv, off));
            pn += __shfl_down_sync(0xffffffffu, pn, off);
        }
        if (lane == 0) { d_key[row] = pv; d_nrmR[row] = pn; }
    }
}

__global__ void k_nrmM(const float* __restrict__ uM) {
    int w = (blockIdx.x * blockDim.x + threadIdx.x) >> 5;
    int lane = threadIdx.x & 31;
    if (w >= NN) return;
    const float* r = uM + w * DD;
    float n = 0.0f;
#pragma unroll
    for (int k = 0; k < DD / 32; k++) { float x = r[lane + 32 * k]; n = fmaf(x, x, n); }
#pragma unroll
    for (int off = 16; off > 0; off >>= 1) n += __shfl_down_sync(0xffffffffu, n, off);
    if (lane == 0) d_nrmM[w] = n;
}

// ---------------- K2: stable ranks via counting --------------------------
__global__ void k_rank() {
    __shared__ float keys[NN];
    int tid = threadIdx.x;
    for (int j = tid; j < NN; j += blockDim.x) keys[j] = d_key[j];
    __syncthreads();
    int i = blockIdx.x * blockDim.x + tid;
    float ki = keys[i];
    int r = 0;
    for (int j = 0; j < NN; j++) {
        float kj = keys[j];
        r += (kj < ki) || (kj == ki && j < i);
    }
    d_rank[i] = r;
    d_sidx[r] = i;
}

// ---------------- K split: fp32 -> bf16 hi/lo -----------------------------
__global__ void k_split(const float* __restrict__ uR, const float* __restrict__ uM) {
    int i = blockIdx.x * blockDim.x + threadIdx.x;
    float x = uR[i];
    __nv_bfloat16 h = __float2bfloat16(x);
    d_Rhi[i] = h;
    d_Rlo[i] = __float2bfloat16(x - __bfloat162float(h));
    float y = uM[i];
    __nv_bfloat16 h2 = __float2bfloat16(y);
    d_Mhi[i] = h2;
    d_Mlo[i] = __float2bfloat16(y - __bfloat162float(h2));
}

// ---------------- soft-float math (FMA/ALU pipes, zero MUFU) -------------
__device__ __forceinline__ float soft_exp2(float t) {
    float tc = fmaxf(fminf(t, 126.0f), -126.0f);
    int k = __float2int_rn(tc);
    float f = tc - (float)k;                       // [-0.5, 0.5]
    float p = 1.3333558146e-3f;
    p = fmaf(p, f, 9.6181291076e-3f);
    p = fmaf(p, f, 5.5504108664e-2f);
    p = fmaf(p, f, 2.4022650696e-1f);
    p = fmaf(p, f, 6.9314718056e-1f);
    p = fmaf(p, f, 1.0f);
    return p * __int_as_float((k + 127) << 23);
}

__device__ __forceinline__ float soft_ln(float x) {  // x in [1e-7, 1], natural log
    int i = __float_as_int(x);
    int e = ((i >> 23) & 0xFF) - 127;
    float m = __int_as_float((i & 0x007FFFFF) | 0x3F800000);  // [1,2)
    bool big = m > 1.4142136f;
    m = big ? m * 0.5f : m;
    e += big ? 1 : 0;
    float r = m - 1.0f;                    // [-0.2929, 0.4142]
    float p = 1.0f / 9.0f;
    p = fmaf(p, r, -1.0f / 8.0f);
    p = fmaf(p, r,  1.0f / 7.0f);
    p = fmaf(p, r, -1.0f / 6.0f);
    p = fmaf(p, r,  1.0f / 5.0f);
    p = fmaf(p, r, -1.0f / 4.0f);
    p = fmaf(p, r,  1.0f / 3.0f);
    p = fmaf(p, r, -0.5f);
    p = fmaf(p, r,  1.0f);
    return fmaf((float)e, 0.69314718056f, r * p);
}

// out = sigmoid((logitexp(logp) + log(u/(1-u))) / 0.3), valid for logp <= -0.7
__device__ __forceinline__ float epi_soft(float acc, float na, float nb,
                                          float nhs, float u) {
    float d2 = fmaxf(fmaf(-2.0f, acc, na + nb), 0.0f);
    float logp = d2 * nhs;                                    // <= -8 in practice
    float p = soft_exp2(logp * 1.4426950409f);
    float L = logp + fmaf(0.5f * p, p, p);                    // logp - log(1-p)
    u = fminf(fmaxf(u, 1e-6f), 1.0f - 1e-6f);
    float S = soft_ln(u) - soft_ln(1.0f - u);
    float t = (L + S) * -4.8089834697f;                       // -(z) * log2(e), z=(L+S)/0.3
    float w = soft_exp2(t);                                   // e^{-z}
    float xd = 1.0f + w;
    float y = __int_as_float(0x7EF311C3 - __float_as_int(xd));
    y = y * (2.0f - xd * y);
    y = y * (2.0f - xd * y);
    y = y * (2.0f - xd * y);
    return y;                                                 // 1/(1+w)
}

// ---------------- fused HMMA GEMM + soft epilogue -------------------------
// CTA tile 128x128, 8 warps (2x4), warp tile 64x32, BK=32, double buffered.
// Virtual K = 768 bf16: hi*hi (k0..255), hi*lo, lo*hi.
// SMEM layout per operand tile [128][32]: 8x8 bf16 blocks contiguous (128B):
//   addr = ((row>>3)*4 + (k>>3))*128 + (row&7)*16 + (k&7)*2
#define STAGE 8192
#define SMEM_DYN (4 * STAGE)

__device__ __forceinline__ void ldsm_x4(uint32_t* r, uint32_t addr) {
    asm volatile("ldmatrix.sync.aligned.m8n8.x4.shared.b16 {%0,%1,%2,%3}, [%4];"
                 : "=r"(r[0]), "=r"(r[1]), "=r"(r[2]), "=r"(r[3]) : "r"(addr));
}
__device__ __forceinline__ void mma16816(float* d, const uint32_t* a,
                                         uint32_t b0, uint32_t b1) {
    asm volatile(
        "mma.sync.aligned.m16n8k16.row.col.f32.bf16.bf16.f32 "
        "{%0,%1,%2,%3}, {%4,%5,%6,%7}, {%8,%9}, {%0,%1,%2,%3};"
        : "+f"(d[0]), "+f"(d[1]), "+f"(d[2]), "+f"(d[3])
        : "r"(a[0]), "r"(a[1]), "r"(a[2]), "r"(a[3]), "r"(b0), "r"(b1));
}
__device__ __forceinline__ uint32_t smem_u32(const void* p) {
    uint32_t a;
    asm("{ .reg .u64 t; cvta.to.shared.u64 t, %1; cvt.u32.u64 %0, t; }" : "=r"(a) : "l"(p));
    return a;
}

template<bool TRI>
__global__ void __launch_bounds__(256)
k_hmma(const __nv_bfloat16* __restrict__ Ahi, const __nv_bfloat16* __restrict__ Alo,
       const __nv_bfloat16* __restrict__ Bhi, const __nv_bfloat16* __restrict__ Blo,
       const float* __restrict__ U, const float* __restrict__ gls,
       float* __restrict__ Out)
{
    extern __shared__ __align__(128) char dsm[];
    __shared__ int   shA[128], shB[128];
    __shared__ float snA[128], snB[128];

    const int tid = threadIdx.x;
    const int wid = tid >> 5;
    const int lane = tid & 31;
    const int warp_m = wid & 1;      // 2 row-groups of 64
    const int warp_n = wid >> 1;     // 4 col-groups of 32

    int ta, tb;
    if (TRI) {
        int rem = blockIdx.x; ta = 0;
        while (rem >= (32 - ta)) { rem -= (32 - ta); ta++; }
        tb = ta + rem;
    } else { ta = blockIdx.y; tb = blockIdx.x; }
    const int a0 = ta * 128, b0 = tb * 128;

    if (tid < 128) {
        int a = a0 + tid;
        int ra = TRI ? d_sidx[a] : a;
        shA[tid] = ra;
        snA[tid] = TRI ? d_nrmR[ra] : d_nrmM[ra];
    } else {
        int b = b0 + tid - 128;
        int rb = TRI ? d_sidx[b] : b;
        shB[tid - 128] = rb;
        snB[tid - 128] = d_nrmR[rb];
    }
    __syncthreads();

    uint32_t smA = smem_u32(dsm);
    uint32_t smB = smA + 2 * STAGE;

    // ---- async stage loader: 512 x 16B chunks per operand, 2 per thread ----
    auto load_stage = [&](int ks, int s) {
        int vk = ks * 32;
        int term = vk >> 8;           // 0: hi*hi, 1: hi*lo, 2: lo*hi
        int k0 = vk & 255;
        const __nv_bfloat16* Ap = (term == 2) ? Alo : Ahi;
        const __nv_bfloat16* Bp = (term == 1) ? Blo : Bhi;
        uint32_t sA = smA + s * STAGE;
        uint32_t sB = smB + s * STAGE;
#pragma unroll
        for (int j = 0; j < 2; j++) {
            int idx = tid + j * 256;          // 0..511
            int m = idx >> 2, kc = idx & 3;
            uint32_t off = (uint32_t)(((m >> 3) * 4 + kc) * 128 + (m & 7) * 16);
            const void* ga = Ap + (size_t)shA[m] * DD + k0 + kc * 8;
            asm volatile("cp.async.cg.shared.global [%0], [%1], 16;"
                         :: "r"(sA + off), "l"(ga));
            const void* gb = Bp + (size_t)shB[m] * DD + k0 + kc * 8;
            asm volatile("cp.async.cg.shared.global [%0], [%1], 16;"
                         :: "r"(sB + off), "l"(gb));
        }
        asm volatile("cp.async.commit_group;");
    };

    float acc[4][4][4];
#pragma unroll
    for (int i = 0; i < 4; i++)
#pragma unroll
        for (int j = 0; j < 4; j++)
#pragma unroll
            for (int q = 0; q < 4; q++) acc[i][j][q] = 0.0f;

    const int mat = lane >> 3, ri = lane & 7;
    const uint32_t cA = (uint32_t)((mat & 1) * 512 + (mat >> 1) * 128 + ri * 16);
    const uint32_t cB = (uint32_t)((mat >> 1) * 512 + (mat & 1) * 128 + ri * 16);

    load_stage(0, 0);
    const int NK = 24;
    for (int ks = 0; ks < NK; ks++) {
        int s = ks & 1;
        if (ks + 1 < NK) {
            load_stage(ks + 1, s ^ 1);
            asm volatile("cp.async.wait_group 1;");
        } else {
            asm volatile("cp.async.wait_group 0;");
        }
        __syncthreads();

        uint32_t baseA = smA + s * STAGE + warp_m * 4096 + cA;
        uint32_t baseB = smB + s * STAGE + warp_n * 2048 + cB;
#pragma unroll
        for (int kh = 0; kh < 2; kh++) {
            uint32_t afr[4][4];
#pragma unroll
            for (int mt = 0; mt < 4; mt++)
                ldsm_x4(afr[mt], baseA + mt * 1024 + kh * 256);
            uint32_t bfr[2][4];
#pragma unroll
            for (int h = 0; h < 2; h++)
                ldsm_x4(bfr[h], baseB + h * 1024 + kh * 256);
#pragma unroll
            for (int mt = 0; mt < 4; mt++)
#pragma unroll
                for (int h = 0; h < 2; h++) {
                    mma16816(acc[mt][2 * h],     afr[mt], bfr[h][0], bfr[h][1]);
                    mma16816(acc[mt][2 * h + 1], afr[mt], bfr[h][2], bfr[h][3]);
                }
        }
        __syncthreads();
    }

    // ---- epilogue: soft-float math, direct coalesced v2 loads/stores ----
    float scale = expf(gls[0]);
    float nhs = -0.5f / scale;
    const int rl = lane >> 2, cl = (lane & 3) * 2;

#pragma unroll
    for (int mt = 0; mt < 4; mt++) {
        int lr = warp_m * 64 + mt * 16 + rl;        // local tile row
        float na0 = snA[lr], na1 = snA[lr + 8];
        size_t g0 = (size_t)(a0 + lr) * NN + b0;
        size_t g1 = g0 + (size_t)8 * NN;
#pragma unroll
        for (int ng = 0; ng < 4; ng++) {
            int cc = warp_n * 32 + ng * 8 + cl;
            float nb0 = snB[cc], nb1 = snB[cc + 1];
            float2 u0 = *(const float2*)&U[g0 + cc];
            float2 u1 = *(const float2*)&U[g1 + cc];
            const float* ac = acc[mt][ng];
            float2 o0, o1;
            o0.x = epi_soft(ac[0], na0, nb0, nhs, u0.x);
            o0.y = epi_soft(ac[1], na0, nb1, nhs, u0.y);
            o1.x = epi_soft(ac[2], na1, nb0, nhs, u1.x);
            o1.y = epi_soft(ac[3], na1, nb1, nhs, u1.y);
            *(float2*)&Out[g0 + cc] = o0;           // lower-tri garbage in TRI is
            *(float2*)&Out[g1 + cc] = o1;           // never read by k_permG
        }
    }
}

// ---------------- K4: permute G back to original order -------------------
__global__ void k_permG(float* __restrict__ out0) {
    __shared__ float rowbuf[NN];
    int i = blockIdx.x;
    int a = d_rank[i];
    const float* src = d_Gs + (size_t)a * NN;
    for (int j = threadIdx.x; j < NN; j += blockDim.x) rowbuf[j] = src[j];
    __syncthreads();
    float* dst = out0 + (size_t)i * NN;
    for (int j = threadIdx.x; j < NN; j += blockDim.x) {
        int rj = d_rank[j];
        dst[j] = (rj > a) ? rowbuf[rj] : 0.0f;
    }
}

// ---------------- launch ---------------------------------------------------
extern "C" void kernel_launch(void* const* d_in, const int* in_sizes, int n_in,
                              void* d_out, int out_size) {
    (void)in_sizes; (void)n_in; (void)out_size;
    const float* uR  = (const float*)d_in[0];
    const float* uM  = (const float*)d_in[1];
    const float* gls = (const float*)d_in[2];
    const float* uG  = (const float*)d_in[3];
    const float* uA  = (const float*)d_in[4];
    float* out = (float*)d_out;

    k_keyR<<<NN, 256>>>(uR);
    k_nrmM<<<NN / 8, 256>>>(uM);
    k_split<<<NN * DD / 256, 256>>>(uR, uM);
    k_rank<<<NN / 256, 256>>>();

    __nv_bfloat16 *Rhi, *Rlo, *Mhi, *Mlo;
    cudaGetSymbolAddress((void**)&Rhi, d_Rhi);
    cudaGetSymbolAddress((void**)&Rlo, d_Rlo);
    cudaGetSymbolAddress((void**)&Mhi, d_Mhi);
    cudaGetSymbolAddress((void**)&Mlo, d_Mlo);
    float* Gs;
    cudaGetSymbolAddress((void**)&Gs, d_Gs);

    // G (sorted coords, upper-triangle tiles): 528 CTAs
    k_hmma<true><<<528, 256, SMEM_DYN>>>(Rhi, Rlo, Rhi, Rlo, uG, gls, Gs);
    k_permG<<<NN, 256>>>(out);

    // A: full 32x32 grid
    dim3 gridA(32, 32);
    k_hmma<false><<<gridA, 256, SMEM_DYN>>>(Mhi, Mlo, Rhi, Rlo, uA, gls,
                                            out + (size_t)NN * NN);
}

// round 5
// speedup vs baseline: 2.8534x; 1.1675x over previous
#include <cuda_runtime.h>
#include <cuda_bf16.h>
#include <math.h>
#include <stdint.h>

#define NN 4096
#define DD 256

// ---------------- device scratch (no allocations allowed) ----------------
__device__ float d_key[NN];
__device__ float d_nrmR[NN];
__device__ float d_nrmM[NN];
__device__ int   d_rank[NN];
__device__ int   d_sidx[NN];
__device__ float d_Gs[(size_t)NN * NN];          // G in sorted coords
__device__ __nv_bfloat16 d_Rhi[(size_t)NN * DD];
__device__ __nv_bfloat16 d_Rlo[(size_t)NN * DD];
__device__ __nv_bfloat16 d_Mhi[(size_t)NN * DD];
__device__ __nv_bfloat16 d_Mlo[(size_t)NN * DD];

// ---------------- K1: sort key (BIT-EXACT reduction — do not touch) ------
// Fused: also emits uR hi/lo bf16 split and zeroes d_rank for this row.
__global__ void k_keyR(const float* __restrict__ uR) {
    int row = blockIdx.x;
    int t = threadIdx.x;
    int gi = row * DD + t;
    float x = uR[gi];

    __nv_bfloat16 h = __float2bfloat16(x);
    d_Rhi[gi] = h;
    d_Rlo[gi] = __float2bfloat16(x - __bfloat162float(h));
    if (t == 0) d_rank[row] = 0;

    float q = __fdiv_rn(x, 1.41421356237309515f);
    float p = __fadd_rn(0.5f, __fmul_rn(0.5f, erff(q)));
    float v = logf(p);
    float n = x * x;
#pragma unroll
    for (int off = 16; off > 0; off >>= 1) {
        v = __fadd_rn(v, __shfl_down_sync(0xffffffffu, v, off));
        n += __shfl_down_sync(0xffffffffu, n, off);
    }
    __shared__ float wp[8], wn[8];
    int w = t >> 5, lane = t & 31;
    if (lane == 0) { wp[w] = v; wn[w] = n; }
    __syncthreads();
    if (w == 0) {
        float pv = (lane < 8) ? wp[lane] : 0.0f;
        float pn = (lane < 8) ? wn[lane] : 0.0f;
#pragma unroll
        for (int off = 16; off > 0; off >>= 1) {
            pv = __fadd_rn(pv, __shfl_down_sync(0xffffffffu, pv, off));
            pn += __shfl_down_sync(0xffffffffu, pn, off);
        }
        if (lane == 0) { d_key[row] = pv; d_nrmR[row] = pn; }
    }
}

// ---------------- K1b: uM norms + hi/lo split (fused) ---------------------
__global__ void k_nrmM(const float* __restrict__ uM) {
    int row = blockIdx.x;
    int t = threadIdx.x;
    int gi = row * DD + t;
    float x = uM[gi];
    __nv_bfloat16 h = __float2bfloat16(x);
    d_Mhi[gi] = h;
    d_Mlo[gi] = __float2bfloat16(x - __bfloat162float(h));

    float n = x * x;
#pragma unroll
    for (int off = 16; off > 0; off >>= 1) n += __shfl_down_sync(0xffffffffu, n, off);
    __shared__ float wn[8];
    int w = t >> 5, lane = t & 31;
    if (lane == 0) wn[w] = n;
    __syncthreads();
    if (w == 0) {
        float pn = (lane < 8) ? wn[lane] : 0.0f;
#pragma unroll
        for (int off = 16; off > 0; off >>= 1) pn += __shfl_down_sync(0xffffffffu, pn, off);
        if (lane == 0) d_nrmM[row] = pn;
    }
}

// ---------------- K2: parallel stable ranks (partial counts + atomics) ----
__global__ void k_rankp() {
    __shared__ float keys[256];
    int tid = threadIdx.x;
    int j0 = blockIdx.y * 256;
    keys[tid] = d_key[j0 + tid];
    __syncthreads();
    int i = blockIdx.x * 256 + tid;
    float ki = d_key[i];
    int cnt = 0;
#pragma unroll 8
    for (int jj = 0; jj < 256; jj++) {
        float kj = keys[jj];
        int j = j0 + jj;
        cnt += (kj < ki) || (kj == ki && j < i);
    }
    atomicAdd(&d_rank[i], cnt);
}

__global__ void k_sidx() {
    int i = blockIdx.x * 256 + threadIdx.x;
    d_sidx[d_rank[i]] = i;
}

// ---------------- soft-float math (FMA/ALU pipes, zero MUFU) -------------
__device__ __forceinline__ float soft_exp2(float t) {
    float tc = fmaxf(fminf(t, 126.0f), -126.0f);
    int k = __float2int_rn(tc);
    float f = tc - (float)k;                       // [-0.5, 0.5]
    float p = 1.3333558146e-3f;
    p = fmaf(p, f, 9.6181291076e-3f);
    p = fmaf(p, f, 5.5504108664e-2f);
    p = fmaf(p, f, 2.4022650696e-1f);
    p = fmaf(p, f, 6.9314718056e-1f);
    p = fmaf(p, f, 1.0f);
    return p * __int_as_float((k + 127) << 23);
}

__device__ __forceinline__ float soft_ln(float x) {  // x in [1e-7, 1]
    int i = __float_as_int(x);
    int e = ((i >> 23) & 0xFF) - 127;
    float m = __int_as_float((i & 0x007FFFFF) | 0x3F800000);  // [1,2)
    bool big = m > 1.4142136f;
    m = big ? m * 0.5f : m;
    e += big ? 1 : 0;
    float r = m - 1.0f;
    float p = 1.0f / 9.0f;
    p = fmaf(p, r, -1.0f / 8.0f);
    p = fmaf(p, r,  1.0f / 7.0f);
    p = fmaf(p, r, -1.0f / 6.0f);
    p = fmaf(p, r,  1.0f / 5.0f);
    p = fmaf(p, r, -1.0f / 4.0f);
    p = fmaf(p, r,  1.0f / 3.0f);
    p = fmaf(p, r, -0.5f);
    p = fmaf(p, r,  1.0f);
    return fmaf((float)e, 0.69314718056f, r * p);
}

__device__ __forceinline__ float epi_soft(float acc, float na, float nb,
                                          float nhs, float u) {
    float d2 = fmaxf(fmaf(-2.0f, acc, na + nb), 0.0f);
    float logp = d2 * nhs;
    float p = soft_exp2(logp * 1.4426950409f);
    float L = logp + fmaf(0.5f * p, p, p);                    // logp - log(1-p)
    u = fminf(fmaxf(u, 1e-6f), 1.0f - 1e-6f);
    float S = soft_ln(u) - soft_ln(1.0f - u);
    float t = (L + S) * -4.8089834697f;                       // -z*log2(e)
    float w = soft_exp2(t);
    float xd = 1.0f + w;
    float y = __int_as_float(0x7EF311C3 - __float_as_int(xd));
    y = y * (2.0f - xd * y);
    y = y * (2.0f - xd * y);
    y = y * (2.0f - xd * y);
    return y;
}

// ---------------- merged fused HMMA GEMM + soft epilogue ------------------
// Single launch: blocks [0,528) = G upper-triangle tiles (sorted coords),
// blocks [528,1552) = A tiles. CTA tile 128x128, 8 warps, BK=32,
// 2-stage cp.async double buffer (32KB dyn smem — no opt-in needed).
// Virtual K = 768 bf16 (hi*hi + hi*lo + lo*hi).
#define STAGE 8192
#define SMEM_DYN (4 * STAGE)

__device__ __forceinline__ void ldsm_x4(uint32_t* r, uint32_t addr) {
    asm volatile("ldmatrix.sync.aligned.m8n8.x4.shared.b16 {%0,%1,%2,%3}, [%4];"
                 : "=r"(r[0]), "=r"(r[1]), "=r"(r[2]), "=r"(r[3]) : "r"(addr));
}
__device__ __forceinline__ void mma16816(float* d, const uint32_t* a,
                                         uint32_t b0, uint32_t b1) {
    asm volatile(
        "mma.sync.aligned.m16n8k16.row.col.f32.bf16.bf16.f32 "
        "{%0,%1,%2,%3}, {%4,%5,%6,%7}, {%8,%9}, {%0,%1,%2,%3};"
        : "+f"(d[0]), "+f"(d[1]), "+f"(d[2]), "+f"(d[3])
        : "r"(a[0]), "r"(a[1]), "r"(a[2]), "r"(a[3]), "r"(b0), "r"(b1));
}
__device__ __forceinline__ uint32_t smem_u32(const void* p) {
    uint32_t a;
    asm("{ .reg .u64 t; cvta.to.shared.u64 t, %1; cvt.u32.u64 %0, t; }" : "=r"(a) : "l"(p));
    return a;
}

__global__ void __launch_bounds__(256)
k_gemm(const __nv_bfloat16* __restrict__ Rhi, const __nv_bfloat16* __restrict__ Rlo,
       const __nv_bfloat16* __restrict__ Mhi, const __nv_bfloat16* __restrict__ Mlo,
       const float* __restrict__ uG, const float* __restrict__ uA,
       const float* __restrict__ gls,
       float* __restrict__ Gs, float* __restrict__ OutA)
{
    extern __shared__ __align__(128) char dsm[];
    __shared__ int   shA[128], shB[128];
    __shared__ float snA[128], snB[128];

    const int tid = threadIdx.x;
    const int wid = tid >> 5;
    const int lane = tid & 31;
    const int warp_m = wid & 1;
    const int warp_n = wid >> 1;

    const bool tri = blockIdx.x < 528;
    int ta, tb;
    if (tri) {
        int rem = blockIdx.x; ta = 0;
        while (rem >= (32 - ta)) { rem -= (32 - ta); ta++; }
        tb = ta + rem;
    } else { int r = blockIdx.x - 528; ta = r >> 5; tb = r & 31; }
    const int a0 = ta * 128, b0 = tb * 128;

    const __nv_bfloat16* Ahi = tri ? Rhi : Mhi;
    const __nv_bfloat16* Alo = tri ? Rlo : Mlo;
    const float* U = tri ? uG : uA;
    float* Out = tri ? Gs : OutA;

    if (tid < 128) {
        int a = a0 + tid;
        int ra = tri ? d_sidx[a] : a;
        shA[tid] = ra;
        snA[tid] = tri ? d_nrmR[ra] : d_nrmM[ra];
    } else {
        int b = b0 + tid - 128;
        int rb = tri ? d_sidx[b] : b;
        shB[tid - 128] = rb;
        snB[tid - 128] = d_nrmR[rb];
    }
    __syncthreads();

    uint32_t smA = smem_u32(dsm);
    uint32_t smB = smA + 2 * STAGE;

    auto load_stage = [&](int ks, int s) {
        int vk = ks * 32;
        int term = vk >> 8;           // 0: hi*hi, 1: hi*lo, 2: lo*hi
        int k0 = vk & 255;
        const __nv_bfloat16* Ap = (term == 2) ? Alo : Ahi;
        const __nv_bfloat16* Bp = (term == 1) ? Rlo : Rhi;
        uint32_t sA = smA + s * STAGE;
        uint32_t sB = smB + s * STAGE;
#pragma unroll
        for (int j = 0; j < 2; j++) {
            int idx = tid + j * 256;          // 0..511
            int m = idx >> 2, kc = idx & 3;
            uint32_t off = (uint32_t)(((m >> 3) * 4 + kc) * 128 + (m & 7) * 16);
            const void* ga = Ap + (size_t)shA[m] * DD + k0 + kc * 8;
            asm volatile("cp.async.cg.shared.global [%0], [%1], 16;"
                         :: "r"(sA + off), "l"(ga));
            const void* gb = Bp + (size_t)shB[m] * DD + k0 + kc * 8;
            asm volatile("cp.async.cg.shared.global [%0], [%1], 16;"
                         :: "r"(sB + off), "l"(gb));
        }
        asm volatile("cp.async.commit_group;");
    };

    float acc[4][4][4];
#pragma unroll
    for (int i = 0; i < 4; i++)
#pragma unroll
        for (int j = 0; j < 4; j++)
#pragma unroll
            for (int q = 0; q < 4; q++) acc[i][j][q] = 0.0f;

    const int mat = lane >> 3, ri = lane & 7;
    const uint32_t cA = (uint32_t)((mat & 1) * 512 + (mat >> 1) * 128 + ri * 16);
    const uint32_t cB = (uint32_t)((mat >> 1) * 512 + (mat & 1) * 128 + ri * 16);

    load_stage(0, 0);
    const int NK = 24;
    for (int ks = 0; ks < NK; ks++) {
        int s = ks & 1;
        if (ks + 1 < NK) {
            load_stage(ks + 1, s ^ 1);
            asm volatile("cp.async.wait_group 1;");
        } else {
            asm volatile("cp.async.wait_group 0;");
        }
        __syncthreads();

        uint32_t baseA = smA + s * STAGE + warp_m * 4096 + cA;
        uint32_t baseB = smB + s * STAGE + warp_n * 2048 + cB;
#pragma unroll
        for (int kh = 0; kh < 2; kh++) {
            uint32_t afr[4][4];
#pragma unroll
            for (int mt = 0; mt < 4; mt++)
                ldsm_x4(afr[mt], baseA + mt * 1024 + kh * 256);
            uint32_t bfr[2][4];
#pragma unroll
            for (int h = 0; h < 2; h++)
                ldsm_x4(bfr[h], baseB + h * 1024 + kh * 256);
#pragma unroll
            for (int mt = 0; mt < 4; mt++)
#pragma unroll
                for (int h = 0; h < 2; h++) {
                    mma16816(acc[mt][2 * h],     afr[mt], bfr[h][0], bfr[h][1]);
                    mma16816(acc[mt][2 * h + 1], afr[mt], bfr[h][2], bfr[h][3]);
                }
        }
        __syncthreads();
    }

    // ---- epilogue: soft-float math, coalesced v2 loads/stores ----
    float scale = expf(gls[0]);
    float nhs = -0.5f / scale;
    const int rl = lane >> 2, cl = (lane & 3) * 2;

#pragma unroll
    for (int mt = 0; mt < 4; mt++) {
        int lr = warp_m * 64 + mt * 16 + rl;
        float na0 = snA[lr], na1 = snA[lr + 8];
        size_t g0 = (size_t)(a0 + lr) * NN + b0;
        size_t g1 = g0 + (size_t)8 * NN;
#pragma unroll
        for (int ng = 0; ng < 4; ng++) {
            int cc = warp_n * 32 + ng * 8 + cl;
            float nb0 = snB[cc], nb1 = snB[cc + 1];
            float2 u0 = *(const float2*)&U[g0 + cc];
            float2 u1 = *(const float2*)&U[g1 + cc];
            const float* ac = acc[mt][ng];
            float2 o0, o1;
            o0.x = epi_soft(ac[0], na0, nb0, nhs, u0.x);
            o0.y = epi_soft(ac[1], na0, nb1, nhs, u0.y);
            o1.x = epi_soft(ac[2], na1, nb0, nhs, u1.x);
            o1.y = epi_soft(ac[3], na1, nb1, nhs, u1.y);
            *(float2*)&Out[g0 + cc] = o0;      // lower-tri garbage in tri tiles
            *(float2*)&Out[g1 + cc] = o1;      // is never read by k_permG
        }
    }
}

// ---------------- K4: permute G back to original order -------------------
__global__ void k_permG(float* __restrict__ out0) {
    __shared__ float rowbuf[NN];
    int i = blockIdx.x;
    int a = d_rank[i];
    const float* src = d_Gs + (size_t)a * NN;
    for (int j = threadIdx.x; j < NN; j += blockDim.x) rowbuf[j] = src[j];
    __syncthreads();
    float* dst = out0 + (size_t)i * NN;
    for (int j = threadIdx.x; j < NN; j += blockDim.x) {
        int rj = d_rank[j];
        dst[j] = (rj > a) ? rowbuf[rj] : 0.0f;
    }
}

// ---------------- launch ---------------------------------------------------
extern "C" void kernel_launch(void* const* d_in, const int* in_sizes, int n_in,
                              void* d_out, int out_size) {
    (void)in_sizes; (void)n_in; (void)out_size;
    const float* uR  = (const float*)d_in[0];
    const float* uM  = (const float*)d_in[1];
    const float* gls = (const float*)d_in[2];
    const float* uG  = (const float*)d_in[3];
    const float* uA  = (const float*)d_in[4];
    float* out = (float*)d_out;

    k_keyR<<<NN, 256>>>(uR);          // keys + R split + rank zeroing
    k_nrmM<<<NN, 256>>>(uM);          // M norms + M split
    {
        dim3 g(16, 16);
        k_rankp<<<g, 256>>>();        // parallel partial rank counts
    }
    k_sidx<<<16, 256>>>();

    __nv_bfloat16 *Rhi, *Rlo, *Mhi, *Mlo;
    cudaGetSymbolAddress((void**)&Rhi, d_Rhi);
    cudaGetSymbolAddress((void**)&Rlo, d_Rlo);
    cudaGetSymbolAddress((void**)&Mhi, d_Mhi);
    cudaGetSymbolAddress((void**)&Mlo, d_Mlo);
    float* Gs;
    cudaGetSymbolAddress((void**)&Gs, d_Gs);

    // merged G (528 triangle tiles) + A (1024 tiles) in one launch
    k_gemm<<<1552, 256, SMEM_DYN>>>(Rhi, Rlo, Mhi, Mlo, uG, uA, gls,
                                    Gs, out + (size_t)NN * NN);
    k_permG<<<NN, 256>>>(out);
}

// round 6
// speedup vs baseline: 2.9310x; 1.0272x over previous
#include <cuda_runtime.h>
#include <cuda_bf16.h>
#include <math.h>
#include <stdint.h>

#define NN 4096
#define DD 256

// ---------------- device scratch (no allocations allowed) ----------------
__device__ float d_key[NN];
__device__ float d_nrmR[NN];
__device__ float d_nrmM[NN];
__device__ int   d_rank[NN];
__device__ int   d_sidx[NN];
__device__ float d_Gs[(size_t)NN * NN];          // G in sorted coords
__device__ __nv_bfloat16 d_Rhi[(size_t)NN * DD];
__device__ __nv_bfloat16 d_Rlo[(size_t)NN * DD];
__device__ __nv_bfloat16 d_Mhi[(size_t)NN * DD];
__device__ __nv_bfloat16 d_Mlo[(size_t)NN * DD];

// ---------------- K1: merged prologue -------------------------------------
// blocks [0,NN): sort key (BIT-EXACT reduction — do not touch) + uR norms
//                + uR hi/lo split + rank zeroing
// blocks [NN,2NN): uM norms + uM hi/lo split
__global__ void k_pre(const float* __restrict__ uR, const float* __restrict__ uM) {
    int blk = blockIdx.x;
    int t = threadIdx.x;
    int w = t >> 5, lane = t & 31;

    if (blk < NN) {
        int row = blk;
        int gi = row * DD + t;
        float x = uR[gi];

        __nv_bfloat16 h = __float2bfloat16(x);
        d_Rhi[gi] = h;
        d_Rlo[gi] = __float2bfloat16(x - __bfloat162float(h));
        if (t == 0) d_rank[row] = 0;

        float q = __fdiv_rn(x, 1.41421356237309515f);
        float p = __fadd_rn(0.5f, __fmul_rn(0.5f, erff(q)));
        float v = logf(p);
        float n = x * x;
#pragma unroll
        for (int off = 16; off > 0; off >>= 1) {
            v = __fadd_rn(v, __shfl_down_sync(0xffffffffu, v, off));
            n += __shfl_down_sync(0xffffffffu, n, off);
        }
        __shared__ float wp[8], wn[8];
        if (lane == 0) { wp[w] = v; wn[w] = n; }
        __syncthreads();
        if (w == 0) {
            float pv = (lane < 8) ? wp[lane] : 0.0f;
            float pn = (lane < 8) ? wn[lane] : 0.0f;
#pragma unroll
            for (int off = 16; off > 0; off >>= 1) {
                pv = __fadd_rn(pv, __shfl_down_sync(0xffffffffu, pv, off));
                pn += __shfl_down_sync(0xffffffffu, pn, off);
            }
            if (lane == 0) { d_key[row] = pv; d_nrmR[row] = pn; }
        }
    } else {
        int row = blk - NN;
        int gi = row * DD + t;
        float x = uM[gi];
        __nv_bfloat16 h = __float2bfloat16(x);
        d_Mhi[gi] = h;
        d_Mlo[gi] = __float2bfloat16(x - __bfloat162float(h));

        float n = x * x;
#pragma unroll
        for (int off = 16; off > 0; off >>= 1) n += __shfl_down_sync(0xffffffffu, n, off);
        __shared__ float wn2[8];
        if (lane == 0) wn2[w] = n;
        __syncthreads();
        if (w == 0) {
            float pn = (lane < 8) ? wn2[lane] : 0.0f;
#pragma unroll
            for (int off = 16; off > 0; off >>= 1) pn += __shfl_down_sync(0xffffffffu, pn, off);
            if (lane == 0) d_nrmM[row] = pn;
        }
    }
}

// ---------------- K2: parallel stable ranks (partial counts + atomics) ----
__global__ void k_rankp() {
    __shared__ float keys[256];
    int tid = threadIdx.x;
    int j0 = blockIdx.y * 256;
    keys[tid] = d_key[j0 + tid];
    __syncthreads();
    int i = blockIdx.x * 256 + tid;
    float ki = d_key[i];
    int cnt = 0;
#pragma unroll 8
    for (int jj = 0; jj < 256; jj++) {
        float kj = keys[jj];
        int j = j0 + jj;
        cnt += (kj < ki) || (kj == ki && j < i);
    }
    atomicAdd(&d_rank[i], cnt);
}

__global__ void k_sidx() {
    int i = blockIdx.x * 256 + threadIdx.x;
    d_sidx[d_rank[i]] = i;
}

// ---------------- soft-float math (FMA/ALU pipes, zero MUFU) -------------
__device__ __forceinline__ float soft_exp2(float t) {
    float tc = fmaxf(fminf(t, 126.0f), -126.0f);
    int k = __float2int_rn(tc);
    float f = tc - (float)k;                       // [-0.5, 0.5]
    float p = 1.3333558146e-3f;
    p = fmaf(p, f, 9.6181291076e-3f);
    p = fmaf(p, f, 5.5504108664e-2f);
    p = fmaf(p, f, 2.4022650696e-1f);
    p = fmaf(p, f, 6.9314718056e-1f);
    p = fmaf(p, f, 1.0f);
    return p * __int_as_float((k + 127) << 23);
}

__device__ __forceinline__ float soft_ln(float x) {  // x in [1e-7, 1]
    int i = __float_as_int(x);
    int e = ((i >> 23) & 0xFF) - 127;
    float m = __int_as_float((i & 0x007FFFFF) | 0x3F800000);  // [1,2)
    bool big = m > 1.4142136f;
    m = big ? m * 0.5f : m;
    e += big ? 1 : 0;
    float r = m - 1.0f;
    float p = 1.0f / 9.0f;
    p = fmaf(p, r, -1.0f / 8.0f);
    p = fmaf(p, r,  1.0f / 7.0f);
    p = fmaf(p, r, -1.0f / 6.0f);
    p = fmaf(p, r,  1.0f / 5.0f);
    p = fmaf(p, r, -1.0f / 4.0f);
    p = fmaf(p, r,  1.0f / 3.0f);
    p = fmaf(p, r, -0.5f);
    p = fmaf(p, r,  1.0f);
    return fmaf((float)e, 0.69314718056f, r * p);
}

__device__ __forceinline__ float epi_soft(float acc, float na, float nb,
                                          float nhs, float u) {
    float d2 = fmaxf(fmaf(-2.0f, acc, na + nb), 0.0f);
    float logp = d2 * nhs;
    float p = soft_exp2(logp * 1.4426950409f);
    float L = logp + fmaf(0.5f * p, p, p);                    // logp - log(1-p)
    u = fminf(fmaxf(u, 1e-6f), 1.0f - 1e-6f);
    float S = soft_ln(u) - soft_ln(1.0f - u);
    float t = (L + S) * -4.8089834697f;                       // -z*log2(e)
    float w = soft_exp2(t);
    float xd = 1.0f + w;
    float y = __int_as_float(0x7EF311C3 - __float_as_int(xd));
    y = y * (2.0f - xd * y);
    y = y * (2.0f - xd * y);
    y = y * (2.0f - xd * y);
    return y;
}

// ---------------- merged fused HMMA GEMM + soft epilogue ------------------
// Single launch: blocks [0,528) = G upper-triangle tiles (sorted coords),
// blocks [528,1552) = A tiles. CTA tile 128x128, 8 warps, BK=32,
// 3-stage cp.async pipeline (48KB dyn smem, opt-in attribute), single
// __syncthreads per iteration. Virtual K = 768 bf16 (hi*hi + hi*lo + lo*hi).
#define STAGE_T 16384                 // A(8KB) + B(8KB) per stage
#define SMEM_DYN (3 * STAGE_T)

__device__ __forceinline__ void ldsm_x4(uint32_t* r, uint32_t addr) {
    asm volatile("ldmatrix.sync.aligned.m8n8.x4.shared.b16 {%0,%1,%2,%3}, [%4];"
                 : "=r"(r[0]), "=r"(r[1]), "=r"(r[2]), "=r"(r[3]) : "r"(addr));
}
__device__ __forceinline__ void mma16816(float* d, const uint32_t* a,
                                         uint32_t b0, uint32_t b1) {
    asm volatile(
        "mma.sync.aligned.m16n8k16.row.col.f32.bf16.bf16.f32 "
        "{%0,%1,%2,%3}, {%4,%5,%6,%7}, {%8,%9}, {%0,%1,%2,%3};"
        : "+f"(d[0]), "+f"(d[1]), "+f"(d[2]), "+f"(d[3])
        : "r"(a[0]), "r"(a[1]), "r"(a[2]), "r"(a[3]), "r"(b0), "r"(b1));
}
__device__ __forceinline__ uint32_t smem_u32(const void* p) {
    uint32_t a;
    asm("{ .reg .u64 t; cvta.to.shared.u64 t, %1; cvt.u32.u64 %0, t; }" : "=r"(a) : "l"(p));
    return a;
}

__global__ void __launch_bounds__(256)
k_gemm(const __nv_bfloat16* __restrict__ Rhi, const __nv_bfloat16* __restrict__ Rlo,
       const __nv_bfloat16* __restrict__ Mhi, const __nv_bfloat16* __restrict__ Mlo,
       const float* __restrict__ uG, const float* __restrict__ uA,
       const float* __restrict__ gls,
       float* __restrict__ Gs, float* __restrict__ OutA)
{
    extern __shared__ __align__(128) char dsm[];
    __shared__ int   shA[128], shB[128];
    __shared__ float snA[128], snB[128];

    const int tid = threadIdx.x;
    const int wid = tid >> 5;
    const int lane = tid & 31;
    const int warp_m = wid & 1;
    const int warp_n = wid >> 1;

    const bool tri = blockIdx.x < 528;
    int ta, tb;
    if (tri) {
        int rem = blockIdx.x; ta = 0;
        while (rem >= (32 - ta)) { rem -= (32 - ta); ta++; }
        tb = ta + rem;
    } else { int r = blockIdx.x - 528; ta = r >> 5; tb = r & 31; }
    const int a0 = ta * 128, b0 = tb * 128;

    const __nv_bfloat16* Ahi = tri ? Rhi : Mhi;
    const __nv_bfloat16* Alo = tri ? Rlo : Mlo;
    const float* U = tri ? uG : uA;
    float* Out = tri ? Gs : OutA;

    if (tid < 128) {
        int a = a0 + tid;
        int ra = tri ? d_sidx[a] : a;
        shA[tid] = ra;
        snA[tid] = tri ? d_nrmR[ra] : d_nrmM[ra];
    } else {
        int b = b0 + tid - 128;
        int rb = tri ? d_sidx[b] : b;
        shB[tid - 128] = rb;
        snB[tid - 128] = d_nrmR[rb];
    }
    __syncthreads();

    uint32_t smBase = smem_u32(dsm);

    auto load_stage = [&](int ks, int s) {
        int vk = ks * 32;
        int term = vk >> 8;           // 0: hi*hi, 1: hi*lo, 2: lo*hi
        int k0 = vk & 255;
        const __nv_bfloat16* Ap = (term == 2) ? Alo : Ahi;
        const __nv_bfloat16* Bp = (term == 1) ? Rlo : Rhi;
        uint32_t sA = smBase + s * STAGE_T;
        uint32_t sB = sA + 8192;
#pragma unroll
        for (int j = 0; j < 2; j++) {
            int idx = tid + j * 256;          // 0..511
            int m = idx >> 2, kc = idx & 3;
            uint32_t off = (uint32_t)(((m >> 3) * 4 + kc) * 128 + (m & 7) * 16);
            const void* ga = Ap + (size_t)shA[m] * DD + k0 + kc * 8;
            asm volatile("cp.async.cg.shared.global [%0], [%1], 16;"
                         :: "r"(sA + off), "l"(ga));
            const void* gb = Bp + (size_t)shB[m] * DD + k0 + kc * 8;
            asm volatile("cp.async.cg.shared.global [%0], [%1], 16;"
                         :: "r"(sB + off), "l"(gb));
        }
        asm volatile("cp.async.commit_group;");
    };

    float acc[4][4][4];
#pragma unroll
    for (int i = 0; i < 4; i++)
#pragma unroll
        for (int j = 0; j < 4; j++)
#pragma unroll
            for (int q = 0; q < 4; q++) acc[i][j][q] = 0.0f;

    const int mat = lane >> 3, ri = lane & 7;
    const uint32_t cA = (uint32_t)((mat & 1) * 512 + (mat >> 1) * 128 + ri * 16);
    const uint32_t cB = (uint32_t)((mat >> 1) * 512 + (mat & 1) * 128 + ri * 16);

    const int NK = 24;
    load_stage(0, 0);
    load_stage(1, 1);
    int s = 0;
    for (int ks = 0; ks < NK; ks++) {
        if (ks + 1 < NK) asm volatile("cp.async.wait_group 1;");
        else             asm volatile("cp.async.wait_group 0;");
        __syncthreads();
        // slot (s+2)%3 was fully consumed at iteration ks-1; safe to refill.
        if (ks + 2 < NK) {
            int sn = s + 2; if (sn >= 3) sn -= 3;
            load_stage(ks + 2, sn);
        }

        uint32_t baseA = smBase + s * STAGE_T + warp_m * 4096 + cA;
        uint32_t baseB = smBase + s * STAGE_T + 8192 + warp_n * 2048 + cB;
#pragma unroll
        for (int kh = 0; kh < 2; kh++) {
            uint32_t afr[4][4];
#pragma unroll
            for (int mt = 0; mt < 4; mt++)
                ldsm_x4(afr[mt], baseA + mt * 1024 + kh * 256);
            uint32_t bfr[2][4];
#pragma unroll
            for (int h = 0; h < 2; h++)
                ldsm_x4(bfr[h], baseB + h * 1024 + kh * 256);
#pragma unroll
            for (int mt = 0; mt < 4; mt++)
#pragma unroll
                for (int h = 0; h < 2; h++) {
                    mma16816(acc[mt][2 * h],     afr[mt], bfr[h][0], bfr[h][1]);
                    mma16816(acc[mt][2 * h + 1], afr[mt], bfr[h][2], bfr[h][3]);
                }
        }
        if (++s >= 3) s = 0;
    }

    // ---- epilogue: soft-float math, coalesced v2 loads/stores ----
    float scale = expf(gls[0]);
    float nhs = -0.5f / scale;
    const int rl = lane >> 2, cl = (lane & 3) * 2;

#pragma unroll
    for (int mt = 0; mt < 4; mt++) {
        int lr = warp_m * 64 + mt * 16 + rl;
        float na0 = snA[lr], na1 = snA[lr + 8];
        size_t g0 = (size_t)(a0 + lr) * NN + b0;
        size_t g1 = g0 + (size_t)8 * NN;
#pragma unroll
        for (int ng = 0; ng < 4; ng++) {
            int cc = warp_n * 32 + ng * 8 + cl;
            float nb0 = snB[cc], nb1 = snB[cc + 1];
            float2 u0 = *(const float2*)&U[g0 + cc];
            float2 u1 = *(const float2*)&U[g1 + cc];
            const float* ac = acc[mt][ng];
            float2 o0, o1;
            o0.x = epi_soft(ac[0], na0, nb0, nhs, u0.x);
            o0.y = epi_soft(ac[1], na0, nb1, nhs, u0.y);
            o1.x = epi_soft(ac[2], na1, nb0, nhs, u1.x);
            o1.y = epi_soft(ac[3], na1, nb1, nhs, u1.y);
            *(float2*)&Out[g0 + cc] = o0;      // lower-tri garbage in tri tiles
            *(float2*)&Out[g1 + cc] = o1;      // is never read by k_permG
        }
    }
}

// ---------------- K4: permute G back to original order -------------------
__global__ void k_permG(float* __restrict__ out0) {
    __shared__ float rowbuf[NN];
    int i = blockIdx.x;
    int a = d_rank[i];
    const float* src = d_Gs + (size_t)a * NN;
    for (int j = threadIdx.x; j < NN; j += blockDim.x) rowbuf[j] = src[j];
    __syncthreads();
    float* dst = out0 + (size_t)i * NN;
    for (int j = threadIdx.x; j < NN; j += blockDim.x) {
        int rj = d_rank[j];
        dst[j] = (rj > a) ? rowbuf[rj] : 0.0f;
    }
}

// ---------------- launch ---------------------------------------------------
extern "C" void kernel_launch(void* const* d_in, const int* in_sizes, int n_in,
                              void* d_out, int out_size) {
    (void)in_sizes; (void)n_in; (void)out_size;
    const float* uR  = (const float*)d_in[0];
    const float* uM  = (const float*)d_in[1];
    const float* gls = (const float*)d_in[2];
    const float* uG  = (const float*)d_in[3];
    const float* uA  = (const float*)d_in[4];
    float* out = (float*)d_out;

    // opt-in for 48KB dynamic smem (host-side, capture-legal, idempotent)
    cudaFuncSetAttribute(k_gemm, cudaFuncAttributeMaxDynamicSharedMemorySize, 65536);

    k_pre<<<2 * NN, 256>>>(uR, uM);   // keys + norms + bf16 splits + rank zeroing
    {
        dim3 g(16, 16);
        k_rankp<<<g, 256>>>();        // parallel partial rank counts
    }
    k_sidx<<<16, 256>>>();

    __nv_bfloat16 *Rhi, *Rlo, *Mhi, *Mlo;
    cudaGetSymbolAddress((void**)&Rhi, d_Rhi);
    cudaGetSymbolAddress((void**)&Rlo, d_Rlo);
    cudaGetSymbolAddress((void**)&Mhi, d_Mhi);
    cudaGetSymbolAddress((void**)&Mlo, d_Mlo);
    float* Gs;
    cudaGetSymbolAddress((void**)&Gs, d_Gs);

    // merged G (528 triangle tiles) + A (1024 tiles) in one launch
    k_gemm<<<1552, 256, SMEM_DYN>>>(Rhi, Rlo, Mhi, Mlo, uG, uA, gls,
                                    Gs, out + (size_t)NN * NN);
    k_permG<<<NN, 256>>>(out);
}

// round 7
// speedup vs baseline: 3.5654x; 1.2165x over previous
#include <cuda_runtime.h>
#include <cuda_bf16.h>
#include <math.h>
#include <stdint.h>

#define NN 4096
#define DD 256

// ---------------- device scratch (no allocations allowed) ----------------
__device__ float d_key[NN];
__device__ float d_nrmR[NN];
__device__ float d_nrmM[NN];
__device__ int   d_rank[NN];
__device__ int   d_sidx[NN];
__device__ float d_Gs[(size_t)NN * NN];          // G in sorted coords
__device__ __nv_bfloat16 d_Rhi[(size_t)NN * DD];
__device__ __nv_bfloat16 d_Rlo[(size_t)NN * DD];
__device__ __nv_bfloat16 d_Mhi[(size_t)NN * DD];
__device__ __nv_bfloat16 d_Mlo[(size_t)NN * DD];

// ---------------- K1: merged prologue -------------------------------------
// blocks [0,NN): sort key (BIT-EXACT reduction — do not touch) + uR norms
//                + uR hi/lo split + rank zeroing
// blocks [NN,2NN): uM norms + uM hi/lo split
__global__ void k_pre(const float* __restrict__ uR, const float* __restrict__ uM) {
    int blk = blockIdx.x;
    int t = threadIdx.x;
    int w = t >> 5, lane = t & 31;

    if (blk < NN) {
        int row = blk;
        int gi = row * DD + t;
        float x = uR[gi];

        __nv_bfloat16 h = __float2bfloat16(x);
        d_Rhi[gi] = h;
        d_Rlo[gi] = __float2bfloat16(x - __bfloat162float(h));
        if (t == 0) d_rank[row] = 0;

        float q = __fdiv_rn(x, 1.41421356237309515f);
        float p = __fadd_rn(0.5f, __fmul_rn(0.5f, erff(q)));
        float v = logf(p);
        float n = x * x;
#pragma unroll
        for (int off = 16; off > 0; off >>= 1) {
            v = __fadd_rn(v, __shfl_down_sync(0xffffffffu, v, off));
            n += __shfl_down_sync(0xffffffffu, n, off);
        }
        __shared__ float wp[8], wn[8];
        if (lane == 0) { wp[w] = v; wn[w] = n; }
        __syncthreads();
        if (w == 0) {
            float pv = (lane < 8) ? wp[lane] : 0.0f;
            float pn = (lane < 8) ? wn[lane] : 0.0f;
#pragma unroll
            for (int off = 16; off > 0; off >>= 1) {
                pv = __fadd_rn(pv, __shfl_down_sync(0xffffffffu, pv, off));
                pn += __shfl_down_sync(0xffffffffu, pn, off);
            }
            if (lane == 0) { d_key[row] = pv; d_nrmR[row] = pn; }
        }
    } else {
        int row = blk - NN;
        int gi = row * DD + t;
        float x = uM[gi];
        __nv_bfloat16 h = __float2bfloat16(x);
        d_Mhi[gi] = h;
        d_Mlo[gi] = __float2bfloat16(x - __bfloat162float(h));

        float n = x * x;
#pragma unroll
        for (int off = 16; off > 0; off >>= 1) n += __shfl_down_sync(0xffffffffu, n, off);
        __shared__ float wn2[8];
        if (lane == 0) wn2[w] = n;
        __syncthreads();
        if (w == 0) {
            float pn = (lane < 8) ? wn2[lane] : 0.0f;
#pragma unroll
            for (int off = 16; off > 0; off >>= 1) pn += __shfl_down_sync(0xffffffffu, pn, off);
            if (lane == 0) d_nrmM[row] = pn;
        }
    }
}

// ---------------- K2: parallel stable ranks (partial counts + atomics) ----
__global__ void k_rankp() {
    __shared__ float keys[256];
    int tid = threadIdx.x;
    int j0 = blockIdx.y * 256;
    keys[tid] = d_key[j0 + tid];
    __syncthreads();
    int i = blockIdx.x * 256 + tid;
    float ki = d_key[i];
    int cnt = 0;
#pragma unroll 8
    for (int jj = 0; jj < 256; jj++) {
        float kj = keys[jj];
        int j = j0 + jj;
        cnt += (kj < ki) || (kj == ki && j < i);
    }
    atomicAdd(&d_rank[i], cnt);
}

__global__ void k_sidx() {
    int i = blockIdx.x * 256 + threadIdx.x;
    d_sidx[d_rank[i]] = i;
}

// ---------------- soft-float math (FMA/ALU pipes, zero MUFU) -------------
__device__ __forceinline__ float soft_exp2(float t) {
    float tc = fmaxf(fminf(t, 126.0f), -126.0f);
    int k = __float2int_rn(tc);
    float f = tc - (float)k;                       // [-0.5, 0.5]
    float p = 1.3333558146e-3f;
    p = fmaf(p, f, 9.6181291076e-3f);
    p = fmaf(p, f, 5.5504108664e-2f);
    p = fmaf(p, f, 2.4022650696e-1f);
    p = fmaf(p, f, 6.9314718056e-1f);
    p = fmaf(p, f, 1.0f);
    return p * __int_as_float((k + 127) << 23);
}

__device__ __forceinline__ float soft_ln(float x) {  // x in [1e-7, 1]
    int i = __float_as_int(x);
    int e = ((i >> 23) & 0xFF) - 127;
    float m = __int_as_float((i & 0x007FFFFF) | 0x3F800000);  // [1,2)
    bool big = m > 1.4142136f;
    m = big ? m * 0.5f : m;
    e += big ? 1 : 0;
    float r = m - 1.0f;
    float p = 1.0f / 9.0f;
    p = fmaf(p, r, -1.0f / 8.0f);
    p = fmaf(p, r,  1.0f / 7.0f);
    p = fmaf(p, r, -1.0f / 6.0f);
    p = fmaf(p, r,  1.0f / 5.0f);
    p = fmaf(p, r, -1.0f / 4.0f);
    p = fmaf(p, r,  1.0f / 3.0f);
    p = fmaf(p, r, -0.5f);
    p = fmaf(p, r,  1.0f);
    return fmaf((float)e, 0.69314718056f, r * p);
}

__device__ __forceinline__ float epi_soft(float acc, float na, float nb,
                                          float nhs, float u) {
    float d2 = fmaxf(fmaf(-2.0f, acc, na + nb), 0.0f);
    float logp = d2 * nhs;
    float p = soft_exp2(logp * 1.4426950409f);
    float L = logp + fmaf(0.5f * p, p, p);                    // logp - log(1-p)
    u = fminf(fmaxf(u, 1e-6f), 1.0f - 1e-6f);
    float S = soft_ln(u) - soft_ln(1.0f - u);
    float t = (L + S) * -4.8089834697f;                       // -z*log2(e)
    float w = soft_exp2(t);
    float xd = 1.0f + w;
    float y = __int_as_float(0x7EF311C3 - __float_as_int(xd));
    y = y * (2.0f - xd * y);
    y = y * (2.0f - xd * y);
    y = y * (2.0f - xd * y);
    return y;
}

// ---------------- merged fused HMMA GEMM + soft epilogue ------------------
// Single launch: blocks [0,528) = G upper-triangle tiles (sorted coords),
// blocks [528,1552) = A tiles. CTA tile 128x128, 8 warps, BK=32.
// FUSED-TERM stages: each 32KB stage holds Ahi,Alo,Bhi,Blo for one k-chunk;
// all 3 split terms (hi*hi + hi*lo + lo*hi) computed per stage.
// 8 mainloop iterations, 3-stage cp.async pipeline (96KB dyn smem).
#define STAGE_T 32768
#define SMEM_DYN (3 * STAGE_T)

__device__ __forceinline__ void ldsm_x4(uint32_t* r, uint32_t addr) {
    asm volatile("ldmatrix.sync.aligned.m8n8.x4.shared.b16 {%0,%1,%2,%3}, [%4];"
                 : "=r"(r[0]), "=r"(r[1]), "=r"(r[2]), "=r"(r[3]) : "r"(addr));
}
__device__ __forceinline__ void mma16816(float* d, const uint32_t* a,
                                         uint32_t b0, uint32_t b1) {
    asm volatile(
        "mma.sync.aligned.m16n8k16.row.col.f32.bf16.bf16.f32 "
        "{%0,%1,%2,%3}, {%4,%5,%6,%7}, {%8,%9}, {%0,%1,%2,%3};"
        : "+f"(d[0]), "+f"(d[1]), "+f"(d[2]), "+f"(d[3])
        : "r"(a[0]), "r"(a[1]), "r"(a[2]), "r"(a[3]), "r"(b0), "r"(b1));
}
__device__ __forceinline__ uint32_t smem_u32(const void* p) {
    uint32_t a;
    asm("{ .reg .u64 t; cvta.to.shared.u64 t, %1; cvt.u32.u64 %0, t; }" : "=r"(a) : "l"(p));
    return a;
}

__global__ void __launch_bounds__(256, 2)
k_gemm(const __nv_bfloat16* __restrict__ Rhi, const __nv_bfloat16* __restrict__ Rlo,
       const __nv_bfloat16* __restrict__ Mhi, const __nv_bfloat16* __restrict__ Mlo,
       const float* __restrict__ uG, const float* __restrict__ uA,
       const float* __restrict__ gls,
       float* __restrict__ Gs, float* __restrict__ OutA)
{
    extern __shared__ __align__(128) char dsm[];
    __shared__ int   shA[128], shB[128];
    __shared__ float snA[128], snB[128];

    const int tid = threadIdx.x;
    const int wid = tid >> 5;
    const int lane = tid & 31;
    const int warp_m = wid & 1;
    const int warp_n = wid >> 1;

    const bool tri = blockIdx.x < 528;
    int ta, tb;
    if (tri) {
        int rem = blockIdx.x; ta = 0;
        while (rem >= (32 - ta)) { rem -= (32 - ta); ta++; }
        tb = ta + rem;
    } else { int r = blockIdx.x - 528; ta = r >> 5; tb = r & 31; }
    const int a0 = ta * 128, b0 = tb * 128;

    const __nv_bfloat16* Ahi = tri ? Rhi : Mhi;
    const __nv_bfloat16* Alo = tri ? Rlo : Mlo;
    const float* U = tri ? uG : uA;
    float* Out = tri ? Gs : OutA;

    if (tid < 128) {
        int a = a0 + tid;
        int ra = tri ? d_sidx[a] : a;
        shA[tid] = ra;
        snA[tid] = tri ? d_nrmR[ra] : d_nrmM[ra];
    } else {
        int b = b0 + tid - 128;
        int rb = tri ? d_sidx[b] : b;
        shB[tid - 128] = rb;
        snB[tid - 128] = d_nrmR[rb];
    }
    __syncthreads();

    uint32_t smBase = smem_u32(dsm);

    // stage slots: [Ahi 8K][Alo 8K][Bhi 8K][Blo 8K]
    auto load_stage = [&](int ks, int s) {
        int k0 = ks * 32;
        uint32_t sAh = smBase + s * STAGE_T;
#pragma unroll
        for (int j = 0; j < 2; j++) {
            int idx = tid + j * 256;          // 0..511
            int m = idx >> 2, kc = idx & 3;
            uint32_t off = (uint32_t)(((m >> 3) * 4 + kc) * 128 + (m & 7) * 16);
            size_t goA = (size_t)shA[m] * DD + k0 + kc * 8;
            size_t goB = (size_t)shB[m] * DD + k0 + kc * 8;
            asm volatile("cp.async.cg.shared.global [%0], [%1], 16;"
                         :: "r"(sAh + off), "l"((const void*)(Ahi + goA)));
            asm volatile("cp.async.cg.shared.global [%0], [%1], 16;"
                         :: "r"(sAh + 8192 + off), "l"((const void*)(Alo + goA)));
            asm volatile("cp.async.cg.shared.global [%0], [%1], 16;"
                         :: "r"(sAh + 16384 + off), "l"((const void*)(Rhi + goB)));
            asm volatile("cp.async.cg.shared.global [%0], [%1], 16;"
                         :: "r"(sAh + 24576 + off), "l"((const void*)(Rlo + goB)));
        }
        asm volatile("cp.async.commit_group;");
    };

    float acc[4][4][4];
#pragma unroll
    for (int i = 0; i < 4; i++)
#pragma unroll
        for (int j = 0; j < 4; j++)
#pragma unroll
            for (int q = 0; q < 4; q++) acc[i][j][q] = 0.0f;

    const int mat = lane >> 3, ri = lane & 7;
    const uint32_t cA = (uint32_t)((mat & 1) * 512 + (mat >> 1) * 128 + ri * 16);
    const uint32_t cB = (uint32_t)((mat >> 1) * 512 + (mat & 1) * 128 + ri * 16);

    const int NK = 8;
    load_stage(0, 0);
    load_stage(1, 1);
    int s = 0;
    for (int ks = 0; ks < NK; ks++) {
        if (ks + 1 < NK) asm volatile("cp.async.wait_group 1;");
        else             asm volatile("cp.async.wait_group 0;");
        __syncthreads();
        // slot (s+2)%3 was fully consumed at iteration ks-1; safe to refill.
        if (ks + 2 < NK) {
            int sn = s + 2; if (sn >= 3) sn -= 3;
            load_stage(ks + 2, sn);
        }

        uint32_t aHi = smBase + s * STAGE_T + warp_m * 4096 + cA;
        uint32_t bHi = smBase + s * STAGE_T + 16384 + warp_n * 2048 + cB;
#pragma unroll
        for (int kh = 0; kh < 2; kh++) {
            uint32_t ah[4][4], al[4][4], bh[2][4], bl[2][4];
#pragma unroll
            for (int mt = 0; mt < 4; mt++)
                ldsm_x4(ah[mt], aHi + mt * 1024 + kh * 256);
#pragma unroll
            for (int h = 0; h < 2; h++) {
                ldsm_x4(bh[h], bHi + h * 1024 + kh * 256);
                ldsm_x4(bl[h], bHi + 8192 + h * 1024 + kh * 256);
            }
            // term 1: hi*hi
#pragma unroll
            for (int mt = 0; mt < 4; mt++)
#pragma unroll
                for (int h = 0; h < 2; h++) {
                    mma16816(acc[mt][2 * h],     ah[mt], bh[h][0], bh[h][1]);
                    mma16816(acc[mt][2 * h + 1], ah[mt], bh[h][2], bh[h][3]);
                }
            // load Alo frags (replaces need for ah afterwards)
#pragma unroll
            for (int mt = 0; mt < 4; mt++)
                ldsm_x4(al[mt], aHi + 8192 + mt * 1024 + kh * 256);
            // term 2: hi*lo
#pragma unroll
            for (int mt = 0; mt < 4; mt++)
#pragma unroll
                for (int h = 0; h < 2; h++) {
                    mma16816(acc[mt][2 * h],     ah[mt], bl[h][0], bl[h][1]);
                    mma16816(acc[mt][2 * h + 1], ah[mt], bl[h][2], bl[h][3]);
                }
            // term 3: lo*hi
#pragma unroll
            for (int mt = 0; mt < 4; mt++)
#pragma unroll
                for (int h = 0; h < 2; h++) {
                    mma16816(acc[mt][2 * h],     al[mt], bh[h][0], bh[h][1]);
                    mma16816(acc[mt][2 * h + 1], al[mt], bh[h][2], bh[h][3]);
                }
        }
        if (++s >= 3) s = 0;
    }

    // ---- epilogue: soft-float math, coalesced v2 loads/stores ----
    float scale = expf(gls[0]);
    float nhs = -0.5f / scale;
    const int rl = lane >> 2, cl = (lane & 3) * 2;

#pragma unroll
    for (int mt = 0; mt < 4; mt++) {
        int lr = warp_m * 64 + mt * 16 + rl;
        float na0 = snA[lr], na1 = snA[lr + 8];
        size_t g0 = (size_t)(a0 + lr) * NN + b0;
        size_t g1 = g0 + (size_t)8 * NN;
#pragma unroll
        for (int ng = 0; ng < 4; ng++) {
            int cc = warp_n * 32 + ng * 8 + cl;
            float nb0 = snB[cc], nb1 = snB[cc + 1];
            float2 u0 = *(const float2*)&U[g0 + cc];
            float2 u1 = *(const float2*)&U[g1 + cc];
            const float* ac = acc[mt][ng];
            float2 o0, o1;
            o0.x = epi_soft(ac[0], na0, nb0, nhs, u0.x);
            o0.y = epi_soft(ac[1], na0, nb1, nhs, u0.y);
            o1.x = epi_soft(ac[2], na1, nb0, nhs, u1.x);
            o1.y = epi_soft(ac[3], na1, nb1, nhs, u1.y);
            *(float2*)&Out[g0 + cc] = o0;      // lower-tri garbage in tri tiles
            *(float2*)&Out[g1 + cc] = o1;      // is never read by k_permG
        }
    }
}

// ---------------- K4: permute G back to original order -------------------
__global__ void k_permG(float* __restrict__ out0) {
    __shared__ float rowbuf[NN];
    int i = blockIdx.x;
    int a = d_rank[i];
    const float* src = d_Gs + (size_t)a * NN;
    for (int j = threadIdx.x; j < NN; j += blockDim.x) rowbuf[j] = src[j];
    __syncthreads();
    float* dst = out0 + (size_t)i * NN;
    for (int j = threadIdx.x; j < NN; j += blockDim.x) {
        int rj = d_rank[j];
        dst[j] = (rj > a) ? rowbuf[rj] : 0.0f;
    }
}

// ---------------- launch ---------------------------------------------------
extern "C" void kernel_launch(void* const* d_in, const int* in_sizes, int n_in,
                              void* d_out, int out_size) {
    (void)in_sizes; (void)n_in; (void)out_size;
    const float* uR  = (const float*)d_in[0];
    const float* uM  = (const float*)d_in[1];
    const float* gls = (const float*)d_in[2];
    const float* uG  = (const float*)d_in[3];
    const float* uA  = (const float*)d_in[4];
    float* out = (float*)d_out;

    // opt-in for 96KB dynamic smem (host-side, capture-legal, idempotent)
    cudaFuncSetAttribute(k_gemm, cudaFuncAttributeMaxDynamicSharedMemorySize, SMEM_DYN);

    k_pre<<<2 * NN, 256>>>(uR, uM);   // keys + norms + bf16 splits + rank zeroing
    {
        dim3 g(16, 16);
        k_rankp<<<g, 256>>>();        // parallel partial rank counts
    }
    k_sidx<<<16, 256>>>();

    __nv_bfloat16 *Rhi, *Rlo, *Mhi, *Mlo;
    cudaGetSymbolAddress((void**)&Rhi, d_Rhi);
    cudaGetSymbolAddress((void**)&Rlo, d_Rlo);
    cudaGetSymbolAddress((void**)&Mhi, d_Mhi);
    cudaGetSymbolAddress((void**)&Mlo, d_Mlo);
    float* Gs;
    cudaGetSymbolAddress((void**)&Gs, d_Gs);

    // merged G (528 triangle tiles) + A (1024 tiles) in one launch
    k_gemm<<<1552, 256, SMEM_DYN>>>(Rhi, Rlo, Mhi, Mlo, uG, uA, gls,
                                    Gs, out + (size_t)NN * NN);
    k_permG<<<NN, 256>>>(out);
}

// round 8
// speedup vs baseline: 3.8441x; 1.0782x over previous
#include <cuda_runtime.h>
#include <cuda_bf16.h>
#include <math.h>
#include <stdint.h>

#define NN 4096
#define DD 256

// ---------------- device scratch (no allocations allowed) ----------------
__device__ float d_key[NN];
__device__ float d_nrmR[NN];
__device__ float d_nrmM[NN];
__device__ int   d_rank[NN];
__device__ int   d_sidx[NN];
__device__ float d_Gs[(size_t)NN * NN];          // G in sorted coords
__device__ __nv_bfloat16 d_Rhi[(size_t)NN * DD];
__device__ __nv_bfloat16 d_Rlo[(size_t)NN * DD];
__device__ __nv_bfloat16 d_Mhi[(size_t)NN * DD];
__device__ __nv_bfloat16 d_Mlo[(size_t)NN * DD];

// ---------------- K1: merged prologue -------------------------------------
// blocks [0,NN): sort key (BIT-EXACT reduction — do not touch) + uR norms
//                + uR hi/lo split + rank zeroing
// blocks [NN,2NN): uM norms + uM hi/lo split
__global__ void k_pre(const float* __restrict__ uR, const float* __restrict__ uM) {
    int blk = blockIdx.x;
    int t = threadIdx.x;
    int w = t >> 5, lane = t & 31;

    if (blk < NN) {
        int row = blk;
        int gi = row * DD + t;
        float x = uR[gi];

        __nv_bfloat16 h = __float2bfloat16(x);
        d_Rhi[gi] = h;
        d_Rlo[gi] = __float2bfloat16(x - __bfloat162float(h));
        if (t == 0) d_rank[row] = 0;

        float q = __fdiv_rn(x, 1.41421356237309515f);
        float p = __fadd_rn(0.5f, __fmul_rn(0.5f, erff(q)));
        float v = logf(p);
        float n = x * x;
#pragma unroll
        for (int off = 16; off > 0; off >>= 1) {
            v = __fadd_rn(v, __shfl_down_sync(0xffffffffu, v, off));
            n += __shfl_down_sync(0xffffffffu, n, off);
        }
        __shared__ float wp[8], wn[8];
        if (lane == 0) { wp[w] = v; wn[w] = n; }
        __syncthreads();
        if (w == 0) {
            float pv = (lane < 8) ? wp[lane] : 0.0f;
            float pn = (lane < 8) ? wn[lane] : 0.0f;
#pragma unroll
            for (int off = 16; off > 0; off >>= 1) {
                pv = __fadd_rn(pv, __shfl_down_sync(0xffffffffu, pv, off));
                pn += __shfl_down_sync(0xffffffffu, pn, off);
            }
            if (lane == 0) { d_key[row] = pv; d_nrmR[row] = pn; }
        }
    } else {
        int row = blk - NN;
        int gi = row * DD + t;
        float x = uM[gi];
        __nv_bfloat16 h = __float2bfloat16(x);
        d_Mhi[gi] = h;
        d_Mlo[gi] = __float2bfloat16(x - __bfloat162float(h));

        float n = x * x;
#pragma unroll
        for (int off = 16; off > 0; off >>= 1) n += __shfl_down_sync(0xffffffffu, n, off);
        __shared__ float wn2[8];
        if (lane == 0) wn2[w] = n;
        __syncthreads();
        if (w == 0) {
            float pn = (lane < 8) ? wn2[lane] : 0.0f;
#pragma unroll
            for (int off = 16; off > 0; off >>= 1) pn += __shfl_down_sync(0xffffffffu, pn, off);
            if (lane == 0) d_nrmM[row] = pn;
        }
    }
}

// ---------------- K2: parallel stable ranks (partial counts + atomics) ----
__global__ void k_rankp() {
    __shared__ float keys[256];
    int tid = threadIdx.x;
    int j0 = blockIdx.y * 256;
    keys[tid] = d_key[j0 + tid];
    __syncthreads();
    int i = blockIdx.x * 256 + tid;
    float ki = d_key[i];
    int cnt = 0;
#pragma unroll 8
    for (int jj = 0; jj < 256; jj++) {
        float kj = keys[jj];
        int j = j0 + jj;
        cnt += (kj < ki) || (kj == ki && j < i);
    }
    atomicAdd(&d_rank[i], cnt);
}

__global__ void k_sidx() {
    int i = blockIdx.x * 256 + threadIdx.x;
    d_sidx[d_rank[i]] = i;
}

// ---------------- epilogue math: FMA soft-exp2 + MUFU logs ---------------
__device__ __forceinline__ float soft_exp2(float t) {
    float tc = fmaxf(fminf(t, 126.0f), -126.0f);
    int k = __float2int_rn(tc);
    float f = tc - (float)k;                       // [-0.5, 0.5]
    float p = 1.3333558146e-3f;
    p = fmaf(p, f, 9.6181291076e-3f);
    p = fmaf(p, f, 5.5504108664e-2f);
    p = fmaf(p, f, 2.4022650696e-1f);
    p = fmaf(p, f, 6.9314718056e-1f);
    p = fmaf(p, f, 1.0f);
    return p * __int_as_float((k + 127) << 23);
}

__device__ __forceinline__ float epi_soft(float acc, float na, float nb,
                                          float nhs, float u) {
    float d2 = fmaxf(fmaf(-2.0f, acc, na + nb), 0.0f);
    float logp = d2 * nhs;
    float p = soft_exp2(logp * 1.4426950409f);                // FMA pipe
    float L = logp + fmaf(0.5f * p, p, p);                    // logp - log(1-p)
    u = fminf(fmaxf(u, 1e-6f), 1.0f - 1e-6f);
    float S = __logf(u) - __logf(1.0f - u);                   // MUFU pipe
    float t = (L + S) * -4.8089834697f;                       // -z*log2(e)
    float w = soft_exp2(t);                                   // FMA pipe
    float xd = 1.0f + w;
    float y = __int_as_float(0x7EF311C3 - __float_as_int(xd));
    y = y * (2.0f - xd * y);
    y = y * (2.0f - xd * y);
    y = y * (2.0f - xd * y);
    return y;
}

// ---------------- merged fused HMMA GEMM + soft epilogue ------------------
// Single launch: blocks [0,528) = G upper-triangle tiles (sorted coords),
// blocks [528,1552) = A tiles. CTA tile 128x128, 8 warps, BK=32.
// FUSED-TERM stages: each 32KB stage holds Ahi,Alo,Bhi,Blo for one k-chunk;
// all 3 split terms (hi*hi + hi*lo + lo*hi) computed per stage.
// All 16 fragment ldsm issued up-front per kh half, then 48 mma back-to-back.
#define STAGE_T 32768
#define SMEM_DYN (3 * STAGE_T)

__device__ __forceinline__ void ldsm_x4(uint32_t* r, uint32_t addr) {
    asm volatile("ldmatrix.sync.aligned.m8n8.x4.shared.b16 {%0,%1,%2,%3}, [%4];"
                 : "=r"(r[0]), "=r"(r[1]), "=r"(r[2]), "=r"(r[3]) : "r"(addr));
}
__device__ __forceinline__ void mma16816(float* d, const uint32_t* a,
                                         uint32_t b0, uint32_t b1) {
    asm volatile(
        "mma.sync.aligned.m16n8k16.row.col.f32.bf16.bf16.f32 "
        "{%0,%1,%2,%3}, {%4,%5,%6,%7}, {%8,%9}, {%0,%1,%2,%3};"
        : "+f"(d[0]), "+f"(d[1]), "+f"(d[2]), "+f"(d[3])
        : "r"(a[0]), "r"(a[1]), "r"(a[2]), "r"(a[3]), "r"(b0), "r"(b1));
}
__device__ __forceinline__ uint32_t smem_u32(const void* p) {
    uint32_t a;
    asm("{ .reg .u64 t; cvta.to.shared.u64 t, %1; cvt.u32.u64 %0, t; }" : "=r"(a) : "l"(p));
    return a;
}

__global__ void __launch_bounds__(256, 2)
k_gemm(const __nv_bfloat16* __restrict__ Rhi, const __nv_bfloat16* __restrict__ Rlo,
       const __nv_bfloat16* __restrict__ Mhi, const __nv_bfloat16* __restrict__ Mlo,
       const float* __restrict__ uG, const float* __restrict__ uA,
       const float* __restrict__ gls,
       float* __restrict__ Gs, float* __restrict__ OutA)
{
    extern __shared__ __align__(128) char dsm[];
    __shared__ int   shA[128], shB[128];
    __shared__ float snA[128], snB[128];

    const int tid = threadIdx.x;
    const int wid = tid >> 5;
    const int lane = tid & 31;
    const int warp_m = wid & 1;
    const int warp_n = wid >> 1;

    const bool tri = blockIdx.x < 528;
    int ta, tb;
    if (tri) {
        int rem = blockIdx.x; ta = 0;
        while (rem >= (32 - ta)) { rem -= (32 - ta); ta++; }
        tb = ta + rem;
    } else { int r = blockIdx.x - 528; ta = r >> 5; tb = r & 31; }
    const int a0 = ta * 128, b0 = tb * 128;

    const __nv_bfloat16* Ahi = tri ? Rhi : Mhi;
    const __nv_bfloat16* Alo = tri ? Rlo : Mlo;
    const float* U = tri ? uG : uA;
    float* Out = tri ? Gs : OutA;

    if (tid < 128) {
        int a = a0 + tid;
        int ra = tri ? d_sidx[a] : a;
        shA[tid] = ra;
        snA[tid] = tri ? d_nrmR[ra] : d_nrmM[ra];
    } else {
        int b = b0 + tid - 128;
        int rb = tri ? d_sidx[b] : b;
        shB[tid - 128] = rb;
        snB[tid - 128] = d_nrmR[rb];
    }
    __syncthreads();

    uint32_t smBase = smem_u32(dsm);

    // stage slots: [Ahi 8K][Alo 8K][Bhi 8K][Blo 8K]
    auto load_stage = [&](int ks, int s) {
        int k0 = ks * 32;
        uint32_t sAh = smBase + s * STAGE_T;
#pragma unroll
        for (int j = 0; j < 2; j++) {
            int idx = tid + j * 256;          // 0..511
            int m = idx >> 2, kc = idx & 3;
            uint32_t off = (uint32_t)(((m >> 3) * 4 + kc) * 128 + (m & 7) * 16);
            size_t goA = (size_t)shA[m] * DD + k0 + kc * 8;
            size_t goB = (size_t)shB[m] * DD + k0 + kc * 8;
            asm volatile("cp.async.cg.shared.global [%0], [%1], 16;"
                         :: "r"(sAh + off), "l"((const void*)(Ahi + goA)));
            asm volatile("cp.async.cg.shared.global [%0], [%1], 16;"
                         :: "r"(sAh + 8192 + off), "l"((const void*)(Alo + goA)));
            asm volatile("cp.async.cg.shared.global [%0], [%1], 16;"
                         :: "r"(sAh + 16384 + off), "l"((const void*)(Rhi + goB)));
            asm volatile("cp.async.cg.shared.global [%0], [%1], 16;"
                         :: "r"(sAh + 24576 + off), "l"((const void*)(Rlo + goB)));
        }
        asm volatile("cp.async.commit_group;");
    };

    float acc[4][4][4];
#pragma unroll
    for (int i = 0; i < 4; i++)
#pragma unroll
        for (int j = 0; j < 4; j++)
#pragma unroll
            for (int q = 0; q < 4; q++) acc[i][j][q] = 0.0f;

    const int mat = lane >> 3, ri = lane & 7;
    const uint32_t cA = (uint32_t)((mat & 1) * 512 + (mat >> 1) * 128 + ri * 16);
    const uint32_t cB = (uint32_t)((mat >> 1) * 512 + (mat & 1) * 128 + ri * 16);

    const int NK = 8;
    load_stage(0, 0);
    load_stage(1, 1);
    int s = 0;
    for (int ks = 0; ks < NK; ks++) {
        if (ks + 1 < NK) asm volatile("cp.async.wait_group 1;");
        else             asm volatile("cp.async.wait_group 0;");
        __syncthreads();
        // slot (s+2)%3 was fully consumed at iteration ks-1; safe to refill.
        if (ks + 2 < NK) {
            int sn = s + 2; if (sn >= 3) sn -= 3;
            load_stage(ks + 2, sn);
        }

        uint32_t aHi = smBase + s * STAGE_T + warp_m * 4096 + cA;
        uint32_t bHi = smBase + s * STAGE_T + 16384 + warp_n * 2048 + cB;
#pragma unroll
        for (int kh = 0; kh < 2; kh++) {
            uint32_t ah[4][4], al[4][4], bh[2][4], bl[2][4];
            // all fragment loads up-front; latency hidden by 96 mma below
#pragma unroll
            for (int mt = 0; mt < 4; mt++)
                ldsm_x4(ah[mt], aHi + mt * 1024 + kh * 256);
#pragma unroll
            for (int h = 0; h < 2; h++) {
                ldsm_x4(bh[h], bHi + h * 1024 + kh * 256);
                ldsm_x4(bl[h], bHi + 8192 + h * 1024 + kh * 256);
            }
#pragma unroll
            for (int mt = 0; mt < 4; mt++)
                ldsm_x4(al[mt], aHi + 8192 + mt * 1024 + kh * 256);
            // term 1: hi*hi
#pragma unroll
            for (int mt = 0; mt < 4; mt++)
#pragma unroll
                for (int h = 0; h < 2; h++) {
                    mma16816(acc[mt][2 * h],     ah[mt], bh[h][0], bh[h][1]);
                    mma16816(acc[mt][2 * h + 1], ah[mt], bh[h][2], bh[h][3]);
                }
            // term 2: hi*lo
#pragma unroll
            for (int mt = 0; mt < 4; mt++)
#pragma unroll
                for (int h = 0; h < 2; h++) {
                    mma16816(acc[mt][2 * h],     ah[mt], bl[h][0], bl[h][1]);
                    mma16816(acc[mt][2 * h + 1], ah[mt], bl[h][2], bl[h][3]);
                }
            // term 3: lo*hi
#pragma unroll
            for (int mt = 0; mt < 4; mt++)
#pragma unroll
                for (int h = 0; h < 2; h++) {
                    mma16816(acc[mt][2 * h],     al[mt], bh[h][0], bh[h][1]);
                    mma16816(acc[mt][2 * h + 1], al[mt], bh[h][2], bh[h][3]);
                }
        }
        if (++s >= 3) s = 0;
    }

    // ---- epilogue: pipe-balanced math, coalesced v2 loads/stores ----
    float scale = expf(gls[0]);
    float nhs = -0.5f / scale;
    const int rl = lane >> 2, cl = (lane & 3) * 2;

#pragma unroll
    for (int mt = 0; mt < 4; mt++) {
        int lr = warp_m * 64 + mt * 16 + rl;
        float na0 = snA[lr], na1 = snA[lr + 8];
        size_t g0 = (size_t)(a0 + lr) * NN + b0;
        size_t g1 = g0 + (size_t)8 * NN;
#pragma unroll
        for (int ng = 0; ng < 4; ng++) {
            int cc = warp_n * 32 + ng * 8 + cl;
            float nb0 = snB[cc], nb1 = snB[cc + 1];
            float2 u0 = *(const float2*)&U[g0 + cc];
            float2 u1 = *(const float2*)&U[g1 + cc];
            const float* ac = acc[mt][ng];
            float2 o0, o1;
            o0.x = epi_soft(ac[0], na0, nb0, nhs, u0.x);
            o0.y = epi_soft(ac[1], na0, nb1, nhs, u0.y);
            o1.x = epi_soft(ac[2], na1, nb0, nhs, u1.x);
            o1.y = epi_soft(ac[3], na1, nb1, nhs, u1.y);
            *(float2*)&Out[g0 + cc] = o0;      // lower-tri garbage in tri tiles
            *(float2*)&Out[g1 + cc] = o1;      // is never read by k_permG
        }
    }
}

// ---------------- K4: permute G back to original order -------------------
__global__ void k_permG(float* __restrict__ out0) {
    __shared__ float rowbuf[NN];
    int i = blockIdx.x;
    int a = d_rank[i];
    const float* src = d_Gs + (size_t)a * NN;
    for (int j = threadIdx.x; j < NN; j += blockDim.x) rowbuf[j] = src[j];
    __syncthreads();
    float* dst = out0 + (size_t)i * NN;
    for (int j = threadIdx.x; j < NN; j += blockDim.x) {
        int rj = d_rank[j];
        dst[j] = (rj > a) ? rowbuf[rj] : 0.0f;
    }
}

// ---------------- launch ---------------------------------------------------
extern "C" void kernel_launch(void* const* d_in, const int* in_sizes, int n_in,
                              void* d_out, int out_size) {
    (void)in_sizes; (void)n_in; (void)out_size;
    const float* uR  = (const float*)d_in[0];
    const float* uM  = (const float*)d_in[1];
    const float* gls = (const float*)d_in[2];
    const float* uG  = (const float*)d_in[3];
    const float* uA  = (const float*)d_in[4];
    float* out = (float*)d_out;

    // opt-in for 96KB dynamic smem (host-side, capture-legal, idempotent)
    cudaFuncSetAttribute(k_gemm, cudaFuncAttributeMaxDynamicSharedMemorySize, SMEM_DYN);

    k_pre<<<2 * NN, 256>>>(uR, uM);   // keys + norms + bf16 splits + rank zeroing
    {
        dim3 g(16, 16);
        k_rankp<<<g, 256>>>();        // parallel partial rank counts
    }
    k_sidx<<<16, 256>>>();

    __nv_bfloat16 *Rhi, *Rlo, *Mhi, *Mlo;
    cudaGetSymbolAddress((void**)&Rhi, d_Rhi);
    cudaGetSymbolAddress((void**)&Rlo, d_Rlo);
    cudaGetSymbolAddress((void**)&Mhi, d_Mhi);
    cudaGetSymbolAddress((void**)&Mlo, d_Mlo);
    float* Gs;
    cudaGetSymbolAddress((void**)&Gs, d_Gs);

    // merged G (528 triangle tiles) + A (1024 tiles) in one launch
    k_gemm<<<1552, 256, SMEM_DYN>>>(Rhi, Rlo, Mhi, Mlo, uG, uA, gls,
                                    Gs, out + (size_t)NN * NN);
    k_permG<<<NN, 512>>>(out);
}

// round 9
// speedup vs baseline: 3.9168x; 1.0189x over previous
#include <cuda_runtime.h>
#include <cuda_bf16.h>
#include <math.h>
#include <stdint.h>

#define NN 4096
#define DD 256

// ---------------- device scratch (no allocations allowed) ----------------
__device__ float d_key[NN];
__device__ float d_nrmR[NN];
__device__ float d_nrmM[NN];
__device__ int   d_rank[NN];
__device__ int   d_sidx[NN];
__device__ float d_Gs[(size_t)NN * NN];          // G in sorted coords
__device__ __nv_bfloat16 d_Rhi[(size_t)NN * DD];
__device__ __nv_bfloat16 d_Rlo[(size_t)NN * DD];
__device__ __nv_bfloat16 d_Mhi[(size_t)NN * DD];
__device__ __nv_bfloat16 d_Mlo[(size_t)NN * DD];

// ---------------- K1: merged prologue -------------------------------------
// blocks [0,NN): sort key (BIT-EXACT reduction — do not touch) + uR norms
//                + uR hi/lo split + rank zeroing
// blocks [NN,2NN): uM norms + uM hi/lo split
__global__ void k_pre(const float* __restrict__ uR, const float* __restrict__ uM) {
    int blk = blockIdx.x;
    int t = threadIdx.x;
    int w = t >> 5, lane = t & 31;

    if (blk < NN) {
        int row = blk;
        int gi = row * DD + t;
        float x = uR[gi];

        __nv_bfloat16 h = __float2bfloat16(x);
        d_Rhi[gi] = h;
        d_Rlo[gi] = __float2bfloat16(x - __bfloat162float(h));
        if (t == 0) d_rank[row] = 0;

        float q = __fdiv_rn(x, 1.41421356237309515f);
        float p = __fadd_rn(0.5f, __fmul_rn(0.5f, erff(q)));
        float v = logf(p);
        float n = x * x;
#pragma unroll
        for (int off = 16; off > 0; off >>= 1) {
            v = __fadd_rn(v, __shfl_down_sync(0xffffffffu, v, off));
            n += __shfl_down_sync(0xffffffffu, n, off);
        }
        __shared__ float wp[8], wn[8];
        if (lane == 0) { wp[w] = v; wn[w] = n; }
        __syncthreads();
        if (w == 0) {
            float pv = (lane < 8) ? wp[lane] : 0.0f;
            float pn = (lane < 8) ? wn[lane] : 0.0f;
#pragma unroll
            for (int off = 16; off > 0; off >>= 1) {
                pv = __fadd_rn(pv, __shfl_down_sync(0xffffffffu, pv, off));
                pn += __shfl_down_sync(0xffffffffu, pn, off);
            }
            if (lane == 0) { d_key[row] = pv; d_nrmR[row] = pn; }
        }
    } else {
        int row = blk - NN;
        int gi = row * DD + t;
        float x = uM[gi];
        __nv_bfloat16 h = __float2bfloat16(x);
        d_Mhi[gi] = h;
        d_Mlo[gi] = __float2bfloat16(x - __bfloat162float(h));

        float n = x * x;
#pragma unroll
        for (int off = 16; off > 0; off >>= 1) n += __shfl_down_sync(0xffffffffu, n, off);
        __shared__ float wn2[8];
        if (lane == 0) wn2[w] = n;
        __syncthreads();
        if (w == 0) {
            float pn = (lane < 8) ? wn2[lane] : 0.0f;
#pragma unroll
            for (int off = 16; off > 0; off >>= 1) pn += __shfl_down_sync(0xffffffffu, pn, off);
            if (lane == 0) d_nrmM[row] = pn;
        }
    }
}

// ---------------- K2: parallel stable ranks (partial counts + atomics) ----
__global__ void k_rankp() {
    __shared__ float keys[256];
    int tid = threadIdx.x;
    int j0 = blockIdx.y * 256;
    keys[tid] = d_key[j0 + tid];
    __syncthreads();
    int i = blockIdx.x * 256 + tid;
    float ki = d_key[i];
    int cnt = 0;
#pragma unroll 8
    for (int jj = 0; jj < 256; jj++) {
        float kj = keys[jj];
        int j = j0 + jj;
        cnt += (kj < ki) || (kj == ki && j < i);
    }
    atomicAdd(&d_rank[i], cnt);
}

__global__ void k_sidx() {
    int i = blockIdx.x * 256 + threadIdx.x;
    d_sidx[d_rank[i]] = i;
}

// ---------------- packed f32x2 epilogue math ------------------------------
typedef unsigned long long ull;
__device__ __forceinline__ ull pk2(float x, float y) {
    ull r; asm("mov.b64 %0, {%1, %2};" : "=l"(r) : "f"(x), "f"(y)); return r;
}
__device__ __forceinline__ void upk2(ull v, float& x, float& y) {
    asm("mov.b64 {%0, %1}, %2;" : "=f"(x), "=f"(y) : "l"(v));
}
__device__ __forceinline__ ull fma2(ull a, ull b, ull c) {
    ull d; asm("fma.rn.f32x2 %0, %1, %2, %3;" : "=l"(d) : "l"(a), "l"(b), "l"(c)); return d;
}
__device__ __forceinline__ ull mul2(ull a, ull b) {
    ull d; asm("mul.rn.f32x2 %0, %1, %2;" : "=l"(d) : "l"(a), "l"(b)); return d;
}
__device__ __forceinline__ ull add2(ull a, ull b) {
    ull d; asm("add.rn.f32x2 %0, %1, %2;" : "=l"(d) : "l"(a), "l"(b)); return d;
}

// packed exp2; valid for t in (-126, 126); round via +1.5*2^23 magic-add
__device__ __forceinline__ ull exp2x2(ull t2) {
    ull m2  = add2(t2, pk2(12582912.0f, 12582912.0f));
    ull fk2 = add2(m2, pk2(-12582912.0f, -12582912.0f));
    ull f2  = fma2(fk2, pk2(-1.0f, -1.0f), t2);          // f = t - rint(t)
    ull p2  = pk2(1.3333558146e-3f, 1.3333558146e-3f);
    p2 = fma2(p2, f2, pk2(9.6181291076e-3f, 9.6181291076e-3f));
    p2 = fma2(p2, f2, pk2(5.5504108664e-2f, 5.5504108664e-2f));
    p2 = fma2(p2, f2, pk2(2.4022650696e-1f, 2.4022650696e-1f));
    p2 = fma2(p2, f2, pk2(6.9314718056e-1f, 6.9314718056e-1f));
    p2 = fma2(p2, f2, pk2(1.0f, 1.0f));
    float mx, my; upk2(m2, mx, my);
    float sx = __int_as_float((__float_as_int(mx) + 127) << 23);  // 2^k
    float sy = __int_as_float((__float_as_int(my) + 127) << 23);
    return mul2(p2, pk2(sx, sy));
}

// two elements: sigmoid((logitexp(logp)+log(u/(1-u)))/0.3), logp <= -0.7
__device__ __forceinline__ float2 epi2(float acx, float acy, float na,
                                       float nb0, float nb1, float nhs,
                                       float ux, float uy) {
    float d2x = fmaxf(fmaf(-2.0f, acx, na + nb0), 0.0f);
    float d2y = fmaxf(fmaf(-2.0f, acy, na + nb1), 0.0f);
    ull logp2 = mul2(pk2(d2x, d2y), pk2(nhs, nhs));
    ull p2 = exp2x2(mul2(logp2, pk2(1.4426950409f, 1.4426950409f)));
    ull L2 = add2(logp2, p2);              // logp - log(1-p) ~= logp + p
    ux = fminf(fmaxf(ux, 1e-6f), 1.0f - 1e-6f);
    uy = fminf(fmaxf(uy, 1e-6f), 1.0f - 1e-6f);
    float Sx = __logf(ux) - __logf(1.0f - ux);            // MUFU pipe
    float Sy = __logf(uy) - __logf(1.0f - uy);
    ull t2 = mul2(add2(L2, pk2(Sx, Sy)), pk2(-4.8089834697f, -4.8089834697f));
    float tx, ty; upk2(t2, tx, ty);
    tx = fminf(tx, 126.0f); ty = fminf(ty, 126.0f);
    ull w2 = exp2x2(pk2(tx, ty));
    ull xd2 = add2(w2, pk2(1.0f, 1.0f));
    float xx, xy; upk2(xd2, xx, xy);
    float2 o;
    o.x = __fdividef(1.0f, xx);                           // MUFU rcp
    o.y = __fdividef(1.0f, xy);
    return o;
}

// ---------------- merged fused HMMA GEMM + packed epilogue ----------------
// Single launch: blocks [0,528) = G upper-triangle tiles (sorted coords),
// blocks [528,1552) = A tiles. CTA tile 128x128, 8 warps, BK=32.
// FUSED-TERM stages: each 32KB stage holds Ahi,Alo,Bhi,Blo for one k-chunk;
// all 3 split terms (hi*hi + hi*lo + lo*hi) computed per stage.
#define STAGE_T 32768
#define SMEM_DYN (3 * STAGE_T)

__device__ __forceinline__ void ldsm_x4(uint32_t* r, uint32_t addr) {
    asm volatile("ldmatrix.sync.aligned.m8n8.x4.shared.b16 {%0,%1,%2,%3}, [%4];"
                 : "=r"(r[0]), "=r"(r[1]), "=r"(r[2]), "=r"(r[3]) : "r"(addr));
}
__device__ __forceinline__ void mma16816(float* d, const uint32_t* a,
                                         uint32_t b0, uint32_t b1) {
    asm volatile(
        "mma.sync.aligned.m16n8k16.row.col.f32.bf16.bf16.f32 "
        "{%0,%1,%2,%3}, {%4,%5,%6,%7}, {%8,%9}, {%0,%1,%2,%3};"
        : "+f"(d[0]), "+f"(d[1]), "+f"(d[2]), "+f"(d[3])
        : "r"(a[0]), "r"(a[1]), "r"(a[2]), "r"(a[3]), "r"(b0), "r"(b1));
}
__device__ __forceinline__ uint32_t smem_u32(const void* p) {
    uint32_t a;
    asm("{ .reg .u64 t; cvta.to.shared.u64 t, %1; cvt.u32.u64 %0, t; }" : "=r"(a) : "l"(p));
    return a;
}

__global__ void __launch_bounds__(256, 2)
k_gemm(const __nv_bfloat16* __restrict__ Rhi, const __nv_bfloat16* __restrict__ Rlo,
       const __nv_bfloat16* __restrict__ Mhi, const __nv_bfloat16* __restrict__ Mlo,
       const float* __restrict__ uG, const float* __restrict__ uA,
       const float* __restrict__ gls,
       float* __restrict__ Gs, float* __restrict__ OutA)
{
    extern __shared__ __align__(128) char dsm[];
    __shared__ int   shA[128], shB[128];
    __shared__ float snA[128], snB[128];

    const int tid = threadIdx.x;
    const int wid = tid >> 5;
    const int lane = tid & 31;
    const int warp_m = wid & 1;
    const int warp_n = wid >> 1;

    const bool tri = blockIdx.x < 528;
    int ta, tb;
    if (tri) {
        int rem = blockIdx.x; ta = 0;
        while (rem >= (32 - ta)) { rem -= (32 - ta); ta++; }
        tb = ta + rem;
    } else { int r = blockIdx.x - 528; ta = r >> 5; tb = r & 31; }
    const int a0 = ta * 128, b0 = tb * 128;

    const __nv_bfloat16* Ahi = tri ? Rhi : Mhi;
    const __nv_bfloat16* Alo = tri ? Rlo : Mlo;
    const float* U = tri ? uG : uA;
    float* Out = tri ? Gs : OutA;

    if (tid < 128) {
        int a = a0 + tid;
        int ra = tri ? d_sidx[a] : a;
        shA[tid] = ra;
        snA[tid] = tri ? d_nrmR[ra] : d_nrmM[ra];
    } else {
        int b = b0 + tid - 128;
        int rb = tri ? d_sidx[b] : b;
        shB[tid - 128] = rb;
        snB[tid - 128] = d_nrmR[rb];
    }
    __syncthreads();

    uint32_t smBase = smem_u32(dsm);

    // stage slots: [Ahi 8K][Alo 8K][Bhi 8K][Blo 8K]
    auto load_stage = [&](int ks, int s) {
        int k0 = ks * 32;
        uint32_t sAh = smBase + s * STAGE_T;
#pragma unroll
        for (int j = 0; j < 2; j++) {
            int idx = tid + j * 256;          // 0..511
            int m = idx >> 2, kc = idx & 3;
            uint32_t off = (uint32_t)(((m >> 3) * 4 + kc) * 128 + (m & 7) * 16);
            size_t goA = (size_t)shA[m] * DD + k0 + kc * 8;
            size_t goB = (size_t)shB[m] * DD + k0 + kc * 8;
            asm volatile("cp.async.cg.shared.global [%0], [%1], 16;"
                         :: "r"(sAh + off), "l"((const void*)(Ahi + goA)));
            asm volatile("cp.async.cg.shared.global [%0], [%1], 16;"
                         :: "r"(sAh + 8192 + off), "l"((const void*)(Alo + goA)));
            asm volatile("cp.async.cg.shared.global [%0], [%1], 16;"
                         :: "r"(sAh + 16384 + off), "l"((const void*)(Rhi + goB)));
            asm volatile("cp.async.cg.shared.global [%0], [%1], 16;"
                         :: "r"(sAh + 24576 + off), "l"((const void*)(Rlo + goB)));
        }
        asm volatile("cp.async.commit_group;");
    };

    float acc[4][4][4];
#pragma unroll
    for (int i = 0; i < 4; i++)
#pragma unroll
        for (int j = 0; j < 4; j++)
#pragma unroll
            for (int q = 0; q < 4; q++) acc[i][j][q] = 0.0f;

    const int mat = lane >> 3, ri = lane & 7;
    const uint32_t cA = (uint32_t)((mat & 1) * 512 + (mat >> 1) * 128 + ri * 16);
    const uint32_t cB = (uint32_t)((mat >> 1) * 512 + (mat & 1) * 128 + ri * 16);

    const int NK = 8;
    load_stage(0, 0);
    load_stage(1, 1);
    int s = 0;
    for (int ks = 0; ks < NK; ks++) {
        if (ks + 1 < NK) asm volatile("cp.async.wait_group 1;");
        else             asm volatile("cp.async.wait_group 0;");
        __syncthreads();
        // slot (s+2)%3 was fully consumed at iteration ks-1; safe to refill.
        if (ks + 2 < NK) {
            int sn = s + 2; if (sn >= 3) sn -= 3;
            load_stage(ks + 2, sn);
        }

        uint32_t aHi = smBase + s * STAGE_T + warp_m * 4096 + cA;
        uint32_t bHi = smBase + s * STAGE_T + 16384 + warp_n * 2048 + cB;
#pragma unroll
        for (int kh = 0; kh < 2; kh++) {
            uint32_t ah[4][4], al[4][4], bh[2][4], bl[2][4];
            // all fragment loads up-front; latency hidden by 96 mma below
#pragma unroll
            for (int mt = 0; mt < 4; mt++)
                ldsm_x4(ah[mt], aHi + mt * 1024 + kh * 256);
#pragma unroll
            for (int h = 0; h < 2; h++) {
                ldsm_x4(bh[h], bHi + h * 1024 + kh * 256);
                ldsm_x4(bl[h], bHi + 8192 + h * 1024 + kh * 256);
            }
#pragma unroll
            for (int mt = 0; mt < 4; mt++)
                ldsm_x4(al[mt], aHi + 8192 + mt * 1024 + kh * 256);
            // term 1: hi*hi
#pragma unroll
            for (int mt = 0; mt < 4; mt++)
#pragma unroll
                for (int h = 0; h < 2; h++) {
                    mma16816(acc[mt][2 * h],     ah[mt], bh[h][0], bh[h][1]);
                    mma16816(acc[mt][2 * h + 1], ah[mt], bh[h][2], bh[h][3]);
                }
            // term 2: hi*lo
#pragma unroll
            for (int mt = 0; mt < 4; mt++)
#pragma unroll
                for (int h = 0; h < 2; h++) {
                    mma16816(acc[mt][2 * h],     ah[mt], bl[h][0], bl[h][1]);
                    mma16816(acc[mt][2 * h + 1], ah[mt], bl[h][2], bl[h][3]);
                }
            // term 3: lo*hi
#pragma unroll
            for (int mt = 0; mt < 4; mt++)
#pragma unroll
                for (int h = 0; h < 2; h++) {
                    mma16816(acc[mt][2 * h],     al[mt], bh[h][0], bh[h][1]);
                    mma16816(acc[mt][2 * h + 1], al[mt], bh[h][2], bh[h][3]);
                }
        }
        if (++s >= 3) s = 0;
    }

    // ---- epilogue: packed f32x2 math, coalesced v2 loads/stores ----
    float scale = expf(gls[0]);
    float nhs = -0.5f / scale;
    const int rl = lane >> 2, cl = (lane & 3) * 2;

#pragma unroll
    for (int mt = 0; mt < 4; mt++) {
        int lr = warp_m * 64 + mt * 16 + rl;
        float na0 = snA[lr], na1 = snA[lr + 8];
        size_t g0 = (size_t)(a0 + lr) * NN + b0;
        size_t g1 = g0 + (size_t)8 * NN;
#pragma unroll
        for (int ng = 0; ng < 4; ng++) {
            int cc = warp_n * 32 + ng * 8 + cl;
            float nb0 = snB[cc], nb1 = snB[cc + 1];
            float2 u0 = *(const float2*)&U[g0 + cc];
            float2 u1 = *(const float2*)&U[g1 + cc];
            const float* ac = acc[mt][ng];
            float2 o0 = epi2(ac[0], ac[1], na0, nb0, nb1, nhs, u0.x, u0.y);
            float2 o1 = epi2(ac[2], ac[3], na1, nb0, nb1, nhs, u1.x, u1.y);
            *(float2*)&Out[g0 + cc] = o0;      // lower-tri garbage in tri tiles
            *(float2*)&Out[g1 + cc] = o1;      // is never read by k_permG
        }
    }
}

// ---------------- K4: permute G back to original order -------------------
__global__ void k_permG(float* __restrict__ out0) {
    __shared__ float rowbuf[NN];
    int i = blockIdx.x;
    int a = d_rank[i];
    const float* src = d_Gs + (size_t)a * NN;
    for (int j = threadIdx.x; j < NN; j += blockDim.x) rowbuf[j] = src[j];
    __syncthreads();
    float* dst = out0 + (size_t)i * NN;
    for (int j = threadIdx.x; j < NN; j += blockDim.x) {
        int rj = d_rank[j];
        dst[j] = (rj > a) ? rowbuf[rj] : 0.0f;
    }
}

// ---------------- launch ---------------------------------------------------
extern "C" void kernel_launch(void* const* d_in, const int* in_sizes, int n_in,
                              void* d_out, int out_size) {
    (void)in_sizes; (void)n_in; (void)out_size;
    const float* uR  = (const float*)d_in[0];
    const float* uM  = (const float*)d_in[1];
    const float* gls = (const float*)d_in[2];
    const float* uG  = (const float*)d_in[3];
    const float* uA  = (const float*)d_in[4];
    float* out = (float*)d_out;

    // opt-in for 96KB dynamic smem (host-side, capture-legal, idempotent)
    cudaFuncSetAttribute(k_gemm, cudaFuncAttributeMaxDynamicSharedMemorySize, SMEM_DYN);

    k_pre<<<2 * NN, 256>>>(uR, uM);   // keys + norms + bf16 splits + rank zeroing
    {
        dim3 g(16, 16);
        k_rankp<<<g, 256>>>();        // parallel partial rank counts
    }
    k_sidx<<<16, 256>>>();

    __nv_bfloat16 *Rhi, *Rlo, *Mhi, *Mlo;
    cudaGetSymbolAddress((void**)&Rhi, d_Rhi);
    cudaGetSymbolAddress((void**)&Rlo, d_Rlo);
    cudaGetSymbolAddress((void**)&Mhi, d_Mhi);
    cudaGetSymbolAddress((void**)&Mlo, d_Mlo);
    float* Gs;
    cudaGetSymbolAddress((void**)&Gs, d_Gs);

    // merged G (528 triangle tiles) + A (1024 tiles) in one launch
    k_gemm<<<1552, 256, SMEM_DYN>>>(Rhi, Rlo, Mhi, Mlo, uG, uA, gls,
                                    Gs, out + (size_t)NN * NN);
    k_permG<<<NN, 512>>>(out);
}